// round 9
// baseline (speedup 1.0000x reference)
#include <cuda_runtime.h>
#include <cuda_fp16.h>
#include <cuda_bf16.h>
#include <math.h>
#include <stdint.h>

#define BB   8
#define NP   2000
#define NNB  64
#define NF   19
#define HH   64
#define NNODE (BB*NP)          // 16000
#define NE   (BB*NP*NNB)       // 1024000
#define NCTA (NNODE/2)         // 8000 edge CTAs (2 nodes / 128 edges each)

// ---------------- device scratch ----------------
__device__ __half g_tbuf[(size_t)NE * HH];   // 131 MB, row-major [edge][j]
__device__ float  g_pooled[NNODE * HH];
__device__ float  g_zA[NNODE * HH];
__device__ float  g_zB[NNODE * HH];
__device__ float  g_colmax[BB * HH];
__device__ double g_sum1[HH], g_sq1[HH], g_sum2[HH], g_sq2[HH];
__device__ double g_U0[BB];

__device__ __forceinline__ const float* selz(int w) {
    return w == 0 ? g_pooled : (w == 1 ? g_zA : g_zB);
}

__device__ __forceinline__ uint32_t smem_u32(const void* p) {
    uint32_t a;
    asm("{ .reg .u64 t; cvta.to.shared.u64 t, %1; cvt.u32.u64 %0, t; }" : "=r"(a) : "l"(p));
    return a;
}

#define SW(o) ((o) ^ (((o) >> 3) & 0x70))

// ---- warp-level bf16 MMA ----
#define MMA16816(c, a, br0, br1) \
    asm volatile("mma.sync.aligned.m16n8k16.row.col.f32.bf16.bf16.f32 " \
                 "{%0,%1,%2,%3}, {%4,%5,%6,%7}, {%8,%9}, {%0,%1,%2,%3};" \
                 : "+f"((c)[0]), "+f"((c)[1]), "+f"((c)[2]), "+f"((c)[3]) \
                 : "r"((a)[0]), "r"((a)[1]), "r"((a)[2]), "r"((a)[3]), \
                   "r"(br0), "r"(br1))

__device__ __forceinline__ void ldmA(uint32_t a[4], const unsigned char* As,
                                     int m0, int k0, int lane) {
    int row = m0 + (lane & 7) + ((lane & 8) ? 8 : 0);
    int kc  = k0 + ((lane & 16) ? 8 : 0);
    uint32_t addr = smem_u32(As + SW(row * 128 + kc * 2));
    asm volatile("ldmatrix.sync.aligned.m8n8.x4.shared.b16 {%0,%1,%2,%3}, [%4];"
                 : "=r"(a[0]), "=r"(a[1]), "=r"(a[2]), "=r"(a[3]) : "r"(addr));
}

__device__ __forceinline__ void ldmB(uint32_t b[4], const unsigned char* Bs,
                                     int n0, int k0, int lane) {
    int row = n0 + (lane & 7) + ((lane & 16) ? 8 : 0);
    int kc  = k0 + ((lane & 8) ? 8 : 0);
    uint32_t addr = smem_u32(Bs + SW(row * 128 + kc * 2));
    asm volatile("ldmatrix.sync.aligned.m8n8.x4.shared.b16 {%0,%1,%2,%3}, [%4];"
                 : "=r"(b[0]), "=r"(b[1]), "=r"(b[2]), "=r"(b[3]) : "r"(addr));
}

template <int KS>
__device__ __forceinline__ void mma_layer(const unsigned char* As, const unsigned char* Bs,
                                          int wid, int lane, float c[2][8][4]) {
#pragma unroll
    for (int i = 0; i < 2; i++)
#pragma unroll
        for (int j = 0; j < 8; j++)
#pragma unroll
            for (int q = 0; q < 4; q++) c[i][j][q] = 0.f;
#pragma unroll
    for (int ks = 0; ks < KS; ks++) {
        int k0 = ks * 16;
        uint32_t a0[4], a1[4];
        ldmA(a0, As, wid * 32, k0, lane);
        ldmA(a1, As, wid * 32 + 16, k0, lane);
#pragma unroll
        for (int jt = 0; jt < 4; jt++) {
            uint32_t b[4];
            ldmB(b, Bs, jt * 16, k0, lane);
            MMA16816(c[0][jt * 2],     a0, b[0], b[1]);
            MMA16816(c[0][jt * 2 + 1], a0, b[2], b[3]);
            MMA16816(c[1][jt * 2],     a1, b[0], b[1]);
            MMA16816(c[1][jt * 2 + 1], a1, b[2], b[3]);
        }
    }
}

// ---------------- zero accumulators ----------------
__global__ void k_zero() {
    int t = threadIdx.x;
    if (t < HH) { g_sum1[t] = 0.0; g_sq1[t] = 0.0; g_sum2[t] = 0.0; g_sq2[t] = 0.0; }
    if (t < BB) g_U0[t] = 0.0;
}

// epilogue helper: fragments -> fp16 global rows + per-column partial (sum, sq) in ps/pq.
// thread holds rows r0, r0+8, r0+16, r0+24 (r0 = wid*32 + lane>>2),
// columns c0 = j*8 + (lane&3)*2 and c0+1. ps/pq[32][33] float2, row = wid*8+(lane>>2),
// col slot = j*4 + (lane&3).
__device__ __forceinline__ void epi_store_stats(
    float c[2][8][4], const float* bias, __half* rowbase,
    float2* ps, float2* pq, int wid, int lane, bool do_store)
{
    const int rcls = wid * 8 + (lane >> 2);
    const int L = lane & 3;
    __half2* gp = (__half2*)rowbase;         // row r0, as half2; col pair index c0>>1
#pragma unroll
    for (int j = 0; j < 8; j++) {
        const int c0 = j * 8 + L * 2;
        float b0v = bias[c0], b1v = bias[c0 + 1];
        __half2 h0 = __floats2half2_rn(c[0][j][0] + b0v, c[0][j][1] + b1v);
        __half2 h1 = __floats2half2_rn(c[0][j][2] + b0v, c[0][j][3] + b1v);
        __half2 h2 = __floats2half2_rn(c[1][j][0] + b0v, c[1][j][1] + b1v);
        __half2 h3 = __floats2half2_rn(c[1][j][2] + b0v, c[1][j][3] + b1v);
        if (do_store) {
            const int cp = c0 >> 1;
            gp[cp]            = h0;   // row r0
            gp[8 * 32 + cp]   = h1;   // row r0+8
            gp[16 * 32 + cp]  = h2;   // row r0+16
            gp[24 * 32 + cp]  = h3;   // row r0+24
        }
        float2 v0 = __half22float2(h0), v1 = __half22float2(h1);
        float2 v2 = __half22float2(h2), v3 = __half22float2(h3);
        float sx = (v0.x + v1.x) + (v2.x + v3.x);
        float sy = (v0.y + v1.y) + (v2.y + v3.y);
        float qx = (v0.x * v0.x + v1.x * v1.x) + (v2.x * v2.x + v3.x * v3.x);
        float qy = (v0.y * v0.y + v1.y * v1.y) + (v2.y * v2.y + v3.y * v3.y);
        ps[rcls * 33 + j * 4 + L] = make_float2(sx, sy);
        pq[rcls * 33 + j * 4 + L] = make_float2(qx, qy);
    }
}

// ---------------- stage 1 ----------------
__global__ __launch_bounds__(128, 4)
void k_edge1(const float* __restrict__ pos, const float* __restrict__ orR,
             const int* __restrict__ nbr,
             const float* __restrict__ w0, const float* __restrict__ b0,
             const float* __restrict__ w1, const float* __restrict__ b1)
{
    __shared__ __align__(128) unsigned char As[16384];
    __shared__ __align__(128) unsigned char Bs[8192];
    __shared__ float2 ps[32 * 33], pq[32 * 33];
    __shared__ float b0s[64], b1s[64], prw[4];

    const int t = threadIdx.x, wid = t >> 5, lane = t & 31;
    const int cta = blockIdx.x;
    const int node0 = cta * 2;
    const int b = node0 / NP;

    if (t < 64) { b0s[t] = b0[t]; b1s[t] = b1[t]; }

    // B-tile: w0 zero-padded to K=32
    for (int idx = t; idx < 1024; idx += 128) {
        int j = idx >> 4, k2 = idx & 15;
        int c0 = 2 * k2, c1 = c0 + 1;
        float v0 = (c0 < NF) ? w0[j * NF + c0] : 0.f;
        float v1 = (c1 < NF) ? w0[j * NF + c1] : 0.f;
        *(__nv_bfloat162*)(Bs + SW(j * 128 + k2 * 4)) = __floats2bfloat162_rn(v0, v1);
    }

    // phase A
    const int node = node0 + (t >> 6);
    const int m    = t & 63;
    const int jn   = nbr[node * NNB + m];
    const int nidx = b * NP + jn;

    float d0 = pos[nidx * 3 + 0] - pos[node * 3 + 0]; d0 -= rintf(d0);
    float d1 = pos[nidx * 3 + 1] - pos[node * 3 + 1]; d1 -= rintf(d1);
    float d2 = pos[nidx * 3 + 2] - pos[node * 3 + 2]; d2 -= rintf(d2);
    float r2 = d0 * d0 + d1 * d1 + d2 * d2 + 1e-12f;
    float R  = sqrtf(r2);
    float inv = 1.0f / R;

    float Ris[9], Rj[9];
#pragma unroll
    for (int k = 0; k < 9; k++) Ris[k] = orR[node * 9 + k];
#pragma unroll
    for (int k = 0; k < 9; k++) Rj[k]  = orR[nidx * 9 + k];

    float f[NF];
    f[0] = d0 * inv; f[1] = d1 * inv; f[2] = d2 * inv; f[3] = R;
#pragma unroll
    for (int j = 0; j < 3; j++) {
        f[4 + j] = f[0] * Ris[j] + f[1] * Ris[3 + j] + f[2] * Ris[6 + j];
        f[7 + j] = f[0] * Rj[j]  + f[1] * Rj[3 + j]  + f[2] * Rj[6 + j];
    }
#pragma unroll
    for (int j = 0; j < 3; j++)
#pragma unroll
        for (int k = 0; k < 3; k++)
            f[10 + j * 3 + k] = Ris[j] * Rj[k] + Ris[3 + j] * Rj[3 + k] + Ris[6 + j] * Rj[6 + k];

    {   // prior: warp shfl reduce
        float tp = 0.01f * inv;
        float tp2 = tp * tp, tp4 = tp2 * tp2, tp8 = tp4 * tp4;
        float pr = tp8 * tp4;
#pragma unroll
        for (int off = 16; off > 0; off >>= 1)
            pr += __shfl_xor_sync(0xffffffffu, pr, off);
        if (lane == 0) prw[wid] = pr;
    }

    // A-tile row t: features bf16, cols 19..31 zero
#pragma unroll
    for (int j2 = 0; j2 < 16; j2++) {
        float v0 = 0.f, v1 = 0.f;
        if (j2 < 9) { v0 = f[2 * j2]; v1 = f[2 * j2 + 1]; }
        else if (j2 == 9) { v0 = f[18]; }
        *(__nv_bfloat162*)(As + SW(t * 128 + j2 * 4)) = __floats2bfloat162_rn(v0, v1);
    }
    __syncthreads();

    // layer 0
    float c[2][8][4];
    mma_layer<2>(As, Bs, wid, lane, c);

    // epilogue 0: relu(+b0) -> As (own warp rows only)
    {
        const int L = lane & 3;
        const int r0 = wid * 32 + (lane >> 2);
#pragma unroll
        for (int j = 0; j < 8; j++) {
            const int c0 = j * 8 + L * 2;
            float b0v = b0s[c0], b1v = b0s[c0 + 1];
            *(__nv_bfloat162*)(As + SW(r0 * 128 + c0 * 2)) =
                __floats2bfloat162_rn(fmaxf(c[0][j][0] + b0v, 0.f), fmaxf(c[0][j][1] + b1v, 0.f));
            *(__nv_bfloat162*)(As + SW((r0 + 8) * 128 + c0 * 2)) =
                __floats2bfloat162_rn(fmaxf(c[0][j][2] + b0v, 0.f), fmaxf(c[0][j][3] + b1v, 0.f));
            *(__nv_bfloat162*)(As + SW((r0 + 16) * 128 + c0 * 2)) =
                __floats2bfloat162_rn(fmaxf(c[1][j][0] + b0v, 0.f), fmaxf(c[1][j][1] + b1v, 0.f));
            *(__nv_bfloat162*)(As + SW((r0 + 24) * 128 + c0 * 2)) =
                __floats2bfloat162_rn(fmaxf(c[1][j][2] + b0v, 0.f), fmaxf(c[1][j][3] + b1v, 0.f));
        }
    }
    __syncthreads();           // all warps done reading Bs(w0)

    for (int idx = t; idx < 2048; idx += 128) {
        int j = idx >> 5, k2 = idx & 31;
        *(__nv_bfloat162*)(Bs + SW(j * 128 + k2 * 4)) =
            __floats2bfloat162_rn(w1[j * 64 + 2 * k2], w1[j * 64 + 2 * k2 + 1]);
    }
    __syncthreads();
    __syncwarp();

    // layer 1
    mma_layer<4>(As, Bs, wid, lane, c);

    __half* rowbase = g_tbuf + ((size_t)cta * 128 + wid * 32 + (lane >> 2)) * 64;
    epi_store_stats(c, b1s, rowbase, ps, pq, wid, lane, true);
    __syncthreads();

    if (t < 32) {
        float2 s = make_float2(0.f, 0.f), q = make_float2(0.f, 0.f);
#pragma unroll 8
        for (int r = 0; r < 32; r++) {
            float2 a = ps[r * 33 + t], qq = pq[r * 33 + t];
            s.x += a.x; s.y += a.y; q.x += qq.x; q.y += qq.y;
        }
        // slot t covers columns: j = t>>2, L = t&3 -> c0 = j*8+L*2
        int c0 = (t >> 2) * 8 + (t & 3) * 2;
        atomicAdd(&g_sum1[c0],     (double)s.x);
        atomicAdd(&g_sum1[c0 + 1], (double)s.y);
        atomicAdd(&g_sq1[c0],      (double)q.x);
        atomicAdd(&g_sq1[c0 + 1],  (double)q.y);
    }
    if (t == 0)
        atomicAdd(&g_U0[b], (double)((prw[0] + prw[1]) + (prw[2] + prw[3])));
}

// ---------------- stage 2 ----------------
__global__ __launch_bounds__(128, 4)
void k_edge2(const float* __restrict__ g1, const float* __restrict__ be1,
             const float* __restrict__ w2, const float* __restrict__ b2)
{
    __shared__ __align__(128) unsigned char As[16384];
    __shared__ __align__(128) unsigned char Bs[8192];
    __shared__ float2 ps[32 * 33], pq[32 * 33];
    __shared__ float b2s[64], sc[64], sh[64];

    const int t = threadIdx.x, wid = t >> 5, lane = t & 31;
    const int cta = blockIdx.x;

    // prefetch scratch row
    uint4 rv[8];
    {
        const uint4* rp = (const uint4*)(g_tbuf + ((size_t)cta * 128 + t) * 64);
#pragma unroll
        for (int q = 0; q < 8; q++) rv[q] = rp[q];
    }
    if (t < 64) {
        b2s[t] = b2[t];
        double mean = g_sum1[t] / (double)NE;
        double var  = g_sq1[t] / (double)NE - mean * mean;
        float istd  = rsqrtf((float)var + 1e-5f);
        float scale = g1[t] * istd;
        sc[t] = scale;
        sh[t] = be1[t] - (float)mean * scale;
    }
    for (int idx = t; idx < 2048; idx += 128) {
        int j = idx >> 5, k2 = idx & 31;
        *(__nv_bfloat162*)(Bs + SW(j * 128 + k2 * 4)) =
            __floats2bfloat162_rn(w2[j * 64 + 2 * k2], w2[j * 64 + 2 * k2 + 1]);
    }
    __syncthreads();

    // convert: BN + relu -> As row t (own warp rows only)
#pragma unroll
    for (int q = 0; q < 8; q++) {
        const __half2* hp = (const __half2*)&rv[q];
#pragma unroll
        for (int u = 0; u < 4; u++) {
            int j = q * 8 + u * 2;
            float2 v = __half22float2(hp[u]);
            float h0 = fmaxf(v.x * sc[j]     + sh[j],     0.f);
            float h1 = fmaxf(v.y * sc[j + 1] + sh[j + 1], 0.f);
            *(__nv_bfloat162*)(As + SW(t * 128 + j * 2)) = __floats2bfloat162_rn(h0, h1);
        }
    }
    __syncwarp();

    float c[2][8][4];
    mma_layer<4>(As, Bs, wid, lane, c);

    __half* rowbase = g_tbuf + ((size_t)cta * 128 + wid * 32 + (lane >> 2)) * 64;
    epi_store_stats(c, b2s, rowbase, ps, pq, wid, lane, true);
    __syncthreads();

    if (t < 32) {
        float2 s = make_float2(0.f, 0.f), q = make_float2(0.f, 0.f);
#pragma unroll 8
        for (int r = 0; r < 32; r++) {
            float2 a = ps[r * 33 + t], qq = pq[r * 33 + t];
            s.x += a.x; s.y += a.y; q.x += qq.x; q.y += qq.y;
        }
        int c0 = (t >> 2) * 8 + (t & 3) * 2;
        atomicAdd(&g_sum2[c0],     (double)s.x);
        atomicAdd(&g_sum2[c0 + 1], (double)s.y);
        atomicAdd(&g_sq2[c0],      (double)q.x);
        atomicAdd(&g_sq2[c0 + 1],  (double)q.y);
    }
}

// ---------------- stage 3 ----------------
__global__ __launch_bounds__(128, 4)
void k_edge3(const float* __restrict__ g2, const float* __restrict__ be2,
             const float* __restrict__ w3, const float* __restrict__ b3)
{
    __shared__ __align__(128) unsigned char As[16384];
    __shared__ __align__(128) unsigned char Bs[8192];
    __shared__ float2 ps[32 * 33], pq[32 * 33];  // pq unused but keeps helper shared
    __shared__ float b3s[64], sc[64], sh[64];

    const int t = threadIdx.x, wid = t >> 5, lane = t & 31;
    const int cta = blockIdx.x;
    const int node0 = cta * 2;

    uint4 rv[8];
    {
        const uint4* rp = (const uint4*)(g_tbuf + ((size_t)cta * 128 + t) * 64);
#pragma unroll
        for (int q = 0; q < 8; q++) rv[q] = rp[q];
    }
    if (t < 64) {
        b3s[t] = b3[t];
        double mean = g_sum2[t] / (double)NE;
        double var  = g_sq2[t] / (double)NE - mean * mean;
        float istd  = rsqrtf((float)var + 1e-5f);
        float scale = g2[t] * istd;
        sc[t] = scale;
        sh[t] = be2[t] - (float)mean * scale;
    }
    for (int idx = t; idx < 2048; idx += 128) {
        int j = idx >> 5, k2 = idx & 31;
        *(__nv_bfloat162*)(Bs + SW(j * 128 + k2 * 4)) =
            __floats2bfloat162_rn(w3[j * 64 + 2 * k2], w3[j * 64 + 2 * k2 + 1]);
    }
    __syncthreads();

#pragma unroll
    for (int q = 0; q < 8; q++) {
        const __half2* hp = (const __half2*)&rv[q];
#pragma unroll
        for (int u = 0; u < 4; u++) {
            int j = q * 8 + u * 2;
            float2 v = __half22float2(hp[u]);
            float h0 = fmaxf(v.x * sc[j]     + sh[j],     0.f);
            float h1 = fmaxf(v.y * sc[j + 1] + sh[j + 1], 0.f);
            *(__nv_bfloat162*)(As + SW(t * 128 + j * 2)) = __floats2bfloat162_rn(h0, h1);
        }
    }
    __syncwarp();

    float c[2][8][4];
    mma_layer<4>(As, Bs, wid, lane, c);

    // partial column sums (no rounding needed — pooled output stays fp32)
    {
        const int rcls = wid * 8 + (lane >> 2);
        const int L = lane & 3;
#pragma unroll
        for (int j = 0; j < 8; j++) {
            float sx = (c[0][j][0] + c[0][j][2]) + (c[1][j][0] + c[1][j][2]);
            float sy = (c[0][j][1] + c[0][j][3]) + (c[1][j][1] + c[1][j][3]);
            ps[rcls * 33 + j * 4 + L] = make_float2(sx, sy);
        }
    }
    __syncthreads();

    // node pooling: rows 0..15 of ps = node0 (edges 0..63), 16..31 = node1
    {
        int nodesel = t >> 6;            // 0 or 1
        int cidx = t & 63;               // output column
        int p = (cidx >> 3) * 4 + ((cidx & 7) >> 1);
        int comp = cidx & 1;
        float s = 0.f;
        int rbase = nodesel * 16;
#pragma unroll 8
        for (int r = 0; r < 16; r++) {
            float2 a = ps[(rbase + r) * 33 + p];
            s += comp ? a.y : a.x;
        }
        g_pooled[(node0 + nodesel) * HH + cidx] = s * (1.0f / NNB) + b3s[cidx];
    }
}

// ---------------- per-feature max over particles ----------------
__global__ __launch_bounds__(1024) void k_colmax(int insel)
{
    const float* z = selz(insel);
    const int b = blockIdx.x;
    const int t = threadIdx.x;
    const int f = t & 63, g = t >> 6;
    float mx = -INFINITY;
    for (int n = g; n < NP; n += 16)
        mx = fmaxf(mx, z[((size_t)b * NP + n) * HH + f]);
    __shared__ float red[1024];
    red[t] = mx;
    __syncthreads();
    if (g == 0) {
        float v = red[f];
#pragma unroll
        for (int r = 1; r < 16; r++) v = fmaxf(v, red[r * 64 + f]);
        g_colmax[b * HH + f] = v;
    }
}

// ---------------- PermEqui1_max ----------------
__global__ __launch_bounds__(256) void k_pe(int insel, int outsel,
    const float* __restrict__ w, const float* __restrict__ bias)
{
    __shared__ float ws[HH * HH], cf[HH], cms[HH];
    const int bx = blockIdx.x;
    const int b  = bx >> 3;
    const int rb = bx & 7;
    const int t  = threadIdx.x;
    const float* zin = selz(insel);
    float* zout = (outsel == 1) ? g_zA : g_zB;

    for (int i = t; i < HH * HH; i += 256) ws[i] = w[i];
    if (t < HH) cms[t] = g_colmax[b * HH + t];
    __syncthreads();

    if (t < HH) {
        float a0 = bias[t], a1 = 0.f, a2 = 0.f, a3 = 0.f;
#pragma unroll
        for (int h = 0; h < HH; h += 4) {
            a0 -= cms[h]     * ws[t * 64 + h];
            a1 -= cms[h + 1] * ws[t * 64 + h + 1];
            a2 -= cms[h + 2] * ws[t * 64 + h + 2];
            a3 -= cms[h + 3] * ws[t * 64 + h + 3];
        }
        cf[t] = (a0 + a1) + (a2 + a3);
    }
    __syncthreads();

    const int n = rb * 256 + t;
    if (n < NP) {
        const float* zr = &zin[((size_t)b * NP + n) * HH];
        float z[HH];
#pragma unroll
        for (int h = 0; h < HH; h++) z[h] = zr[h];
        float* orow = &zout[((size_t)b * NP + n) * HH];
#pragma unroll 4
        for (int fj = 0; fj < HH; fj++) {
            float a0 = cf[fj], a1 = 0.f, a2 = 0.f, a3 = 0.f;
#pragma unroll
            for (int h = 0; h < HH; h += 4) {
                a0 += z[h]     * ws[fj * 64 + h];
                a1 += z[h + 1] * ws[fj * 64 + h + 1];
                a2 += z[h + 2] * ws[fj * 64 + h + 2];
                a3 += z[h + 3] * ws[fj * 64 + h + 3];
            }
            orow[fj] = tanhf((a0 + a1) + (a2 + a3));
        }
    }
}

// ---------------- head ----------------
__global__ __launch_bounds__(64) void k_head(
    const float* __restrict__ r1w, const float* __restrict__ r1b,
    const float* __restrict__ r2w, const float* __restrict__ r2b,
    float* __restrict__ out)
{
    const int b = blockIdx.x;
    const int f = threadIdx.x;
    __shared__ float s[HH], tv[HH];

    s[f] = g_colmax[b * HH + f];
    __syncthreads();

    float a = r1b[f];
#pragma unroll
    for (int h = 0; h < HH; h++) a += s[h] * r1w[f * 64 + h];
    tv[f] = tanhf(a);
    __syncthreads();

    if (f == 0) {
        float e = r2b[0];
        for (int h = 0; h < HH; h++) e += tv[h] * r2w[h];
        out[b] = e + (float)g_U0[b];
    }
}

// ---------------- launcher ----------------
extern "C" void kernel_launch(void* const* d_in, const int* in_sizes, int n_in,
                              void* d_out, int out_size)
{
    const float* pos = (const float*)d_in[0];
    const float* orR = (const float*)d_in[1];
    const int*   nbr = (const int*)  d_in[2];
    const float* w0  = (const float*)d_in[3];
    const float* b0  = (const float*)d_in[4];
    const float* w1  = (const float*)d_in[5];
    const float* b1  = (const float*)d_in[6];
    const float* g1  = (const float*)d_in[7];
    const float* be1 = (const float*)d_in[8];
    const float* w2  = (const float*)d_in[9];
    const float* b2  = (const float*)d_in[10];
    const float* g2  = (const float*)d_in[11];
    const float* be2 = (const float*)d_in[12];
    const float* w3  = (const float*)d_in[13];
    const float* b3  = (const float*)d_in[14];
    const float* p1w = (const float*)d_in[15];
    const float* p1b = (const float*)d_in[16];
    const float* p2w = (const float*)d_in[17];
    const float* p2b = (const float*)d_in[18];
    const float* p3w = (const float*)d_in[19];
    const float* p3b = (const float*)d_in[20];
    const float* r1w = (const float*)d_in[21];
    const float* r1b = (const float*)d_in[22];
    const float* r2w = (const float*)d_in[23];
    const float* r2b = (const float*)d_in[24];
    float* out = (float*)d_out;

    k_zero <<<1, 64>>>();
    k_edge1<<<NCTA, 128>>>(pos, orR, nbr, w0, b0, w1, b1);
    k_edge2<<<NCTA, 128>>>(g1, be1, w2, b2);
    k_edge3<<<NCTA, 128>>>(g2, be2, w3, b3);
    k_colmax<<<BB, 1024>>>(0);
    k_pe   <<<64, 256>>>(0, 1, p1w, p1b);
    k_colmax<<<BB, 1024>>>(1);
    k_pe   <<<64, 256>>>(1, 2, p2w, p2b);
    k_colmax<<<BB, 1024>>>(2);
    k_pe   <<<64, 256>>>(2, 1, p3w, p3b);
    k_colmax<<<BB, 1024>>>(1);
    k_head <<<BB, 64>>>(r1w, r1b, r2w, r2b, out);
}

// round 10
// speedup vs baseline: 1.0733x; 1.0733x over previous
#include <cuda_runtime.h>
#include <cuda_fp16.h>
#include <cuda_bf16.h>
#include <math.h>
#include <stdint.h>

#define BB   8
#define NP   2000
#define NNB  64
#define NF   19
#define HH   64
#define NNODE (BB*NP)          // 16000
#define NE   (BB*NP*NNB)       // 1024000
#define NCTA (NNODE/2)         // 8000 edge CTAs (2 nodes / 128 edges each)

// ---------------- device scratch ----------------
// fragment-native layout: [cta][tid 0..127][32 x half2] — producer/consumer agree on mapping
__device__ __half g_tbuf[(size_t)NE * HH];
__device__ float  g_pooled[NNODE * HH];
__device__ float  g_zA[NNODE * HH];
__device__ float  g_zB[NNODE * HH];
__device__ float  g_colmax[BB * HH];
__device__ double g_sum1[HH], g_sq1[HH], g_sum2[HH], g_sq2[HH];
__device__ double g_U0[BB];

__device__ __forceinline__ const float* selz(int w) {
    return w == 0 ? g_pooled : (w == 1 ? g_zA : g_zB);
}

__device__ __forceinline__ uint32_t smem_u32(const void* p) {
    uint32_t a;
    asm("{ .reg .u64 t; cvta.to.shared.u64 t, %1; cvt.u32.u64 %0, t; }" : "=r"(a) : "l"(p));
    return a;
}

#define SW(o) ((o) ^ (((o) >> 3) & 0x70))

// ---- warp-level bf16 MMA ----
#define MMA16816(c, a, br0, br1) \
    asm volatile("mma.sync.aligned.m16n8k16.row.col.f32.bf16.bf16.f32 " \
                 "{%0,%1,%2,%3}, {%4,%5,%6,%7}, {%8,%9}, {%0,%1,%2,%3};" \
                 : "+f"((c)[0]), "+f"((c)[1]), "+f"((c)[2]), "+f"((c)[3]) \
                 : "r"((a)[0]), "r"((a)[1]), "r"((a)[2]), "r"((a)[3]), \
                   "r"(br0), "r"(br1))

__device__ __forceinline__ void ldmA(uint32_t a[4], const unsigned char* As,
                                     int m0, int k0, int lane) {
    int row = m0 + (lane & 7) + ((lane & 8) ? 8 : 0);
    int kc  = k0 + ((lane & 16) ? 8 : 0);
    uint32_t addr = smem_u32(As + SW(row * 128 + kc * 2));
    asm volatile("ldmatrix.sync.aligned.m8n8.x4.shared.b16 {%0,%1,%2,%3}, [%4];"
                 : "=r"(a[0]), "=r"(a[1]), "=r"(a[2]), "=r"(a[3]) : "r"(addr));
}

__device__ __forceinline__ void ldmB(uint32_t b[4], const unsigned char* Bs,
                                     int n0, int k0, int lane) {
    int row = n0 + (lane & 7) + ((lane & 16) ? 8 : 0);
    int kc  = k0 + ((lane & 8) ? 8 : 0);
    uint32_t addr = smem_u32(Bs + SW(row * 128 + kc * 2));
    asm volatile("ldmatrix.sync.aligned.m8n8.x4.shared.b16 {%0,%1,%2,%3}, [%4];"
                 : "=r"(b[0]), "=r"(b[1]), "=r"(b[2]), "=r"(b[3]) : "r"(addr));
}

template <int KS>
__device__ __forceinline__ void mma_layer(const unsigned char* As, const unsigned char* Bs,
                                          int wid, int lane, float c[2][8][4]) {
#pragma unroll
    for (int i = 0; i < 2; i++)
#pragma unroll
        for (int j = 0; j < 8; j++)
#pragma unroll
            for (int q = 0; q < 4; q++) c[i][j][q] = 0.f;
#pragma unroll
    for (int ks = 0; ks < KS; ks++) {
        int k0 = ks * 16;
        uint32_t a0[4], a1[4];
        ldmA(a0, As, wid * 32, k0, lane);
        ldmA(a1, As, wid * 32 + 16, k0, lane);
#pragma unroll
        for (int jt = 0; jt < 4; jt++) {
            uint32_t b[4];
            ldmB(b, Bs, jt * 16, k0, lane);
            MMA16816(c[0][jt * 2],     a0, b[0], b[1]);
            MMA16816(c[0][jt * 2 + 1], a0, b[2], b[3]);
            MMA16816(c[1][jt * 2],     a1, b[0], b[1]);
            MMA16816(c[1][jt * 2 + 1], a1, b[2], b[3]);
        }
    }
}

// ---------------- zero accumulators ----------------
__global__ void k_zero() {
    int t = threadIdx.x;
    if (t < HH) { g_sum1[t] = 0.0; g_sq1[t] = 0.0; g_sum2[t] = 0.0; g_sq2[t] = 0.0; }
    if (t < BB) g_U0[t] = 0.0;
}

// epilogue: fragments -> fragment-native fp16 scratch (coalesced 128B/thread)
// + per-column partial (sum, sq). slot s = i*16 + j*2 + p.
__device__ __forceinline__ void epi_store_stats(
    float c[2][8][4], const float* bias, __half* tbase,
    float2* ps, float2* pq, int wid, int lane)
{
    const int rcls = wid * 8 + (lane >> 2);
    const int L = lane & 3;
    __half2 o[32];
#pragma unroll
    for (int j = 0; j < 8; j++) {
        const int c0 = j * 8 + L * 2;
        float b0v = bias[c0], b1v = bias[c0 + 1];
        __half2 h0 = __floats2half2_rn(c[0][j][0] + b0v, c[0][j][1] + b1v);
        __half2 h1 = __floats2half2_rn(c[0][j][2] + b0v, c[0][j][3] + b1v);
        __half2 h2 = __floats2half2_rn(c[1][j][0] + b0v, c[1][j][1] + b1v);
        __half2 h3 = __floats2half2_rn(c[1][j][2] + b0v, c[1][j][3] + b1v);
        o[j * 2]          = h0;
        o[j * 2 + 1]      = h1;
        o[16 + j * 2]     = h2;
        o[16 + j * 2 + 1] = h3;
        float2 v0 = __half22float2(h0), v1 = __half22float2(h1);
        float2 v2 = __half22float2(h2), v3 = __half22float2(h3);
        float sx = (v0.x + v1.x) + (v2.x + v3.x);
        float sy = (v0.y + v1.y) + (v2.y + v3.y);
        float qx = (v0.x * v0.x + v1.x * v1.x) + (v2.x * v2.x + v3.x * v3.x);
        float qy = (v0.y * v0.y + v1.y * v1.y) + (v2.y * v2.y + v3.y * v3.y);
        ps[rcls * 33 + j * 4 + L] = make_float2(sx, sy);
        pq[rcls * 33 + j * 4 + L] = make_float2(qx, qy);
    }
#pragma unroll
    for (int q = 0; q < 8; q++) *(uint4*)(tbase + 8 * q) = ((uint4*)o)[q];
}

// consumer: read fragment-native row, BN+relu, scatter into As (own warp rows only)
__device__ __forceinline__ void consume_to_As(
    const uint4 rv[8], unsigned char* As, const float* sc, const float* sh,
    int wid, int lane)
{
    const int rbase = wid * 32 + (lane >> 2);
    const int c0b = (lane & 3) * 2;
#pragma unroll
    for (int s2 = 0; s2 < 8; s2++) {
        const __half2* hp = (const __half2*)&rv[s2];
#pragma unroll
        for (int u = 0; u < 4; u++) {
            int s = s2 * 4 + u;
            int i = s >> 4, j = (s >> 1) & 7, p = s & 1;
            int row = rbase + i * 16 + p * 8;
            int c0 = j * 8 + c0b;
            float2 v = __half22float2(hp[u]);
            float h0 = fmaxf(v.x * sc[c0]     + sh[c0],     0.f);
            float h1 = fmaxf(v.y * sc[c0 + 1] + sh[c0 + 1], 0.f);
            *(__nv_bfloat162*)(As + SW(row * 128 + c0 * 2)) = __floats2bfloat162_rn(h0, h1);
        }
    }
}

// ---------------- stage 1 ----------------
__global__ __launch_bounds__(128, 4)
void k_edge1(const float* __restrict__ pos, const float* __restrict__ orR,
             const int* __restrict__ nbr,
             const float* __restrict__ w0, const float* __restrict__ b0,
             const float* __restrict__ w1, const float* __restrict__ b1)
{
    __shared__ __align__(128) unsigned char As[16384];
    __shared__ __align__(128) unsigned char Bs[8192];
    __shared__ float2 ps[32 * 33], pq[32 * 33];
    __shared__ float b0s[64], b1s[64], prw[4];

    const int t = threadIdx.x, wid = t >> 5, lane = t & 31;
    const int cta = blockIdx.x;
    const int node0 = cta * 2;
    const int b = node0 / NP;

    if (t < 64) { b0s[t] = b0[t]; b1s[t] = b1[t]; }

    for (int idx = t; idx < 1024; idx += 128) {
        int j = idx >> 4, k2 = idx & 15;
        int c0 = 2 * k2, c1 = c0 + 1;
        float v0 = (c0 < NF) ? w0[j * NF + c0] : 0.f;
        float v1 = (c1 < NF) ? w0[j * NF + c1] : 0.f;
        *(__nv_bfloat162*)(Bs + SW(j * 128 + k2 * 4)) = __floats2bfloat162_rn(v0, v1);
    }

    const int node = node0 + (t >> 6);
    const int m    = t & 63;
    const int jn   = nbr[node * NNB + m];
    const int nidx = b * NP + jn;

    float d0 = pos[nidx * 3 + 0] - pos[node * 3 + 0]; d0 -= rintf(d0);
    float d1 = pos[nidx * 3 + 1] - pos[node * 3 + 1]; d1 -= rintf(d1);
    float d2 = pos[nidx * 3 + 2] - pos[node * 3 + 2]; d2 -= rintf(d2);
    float r2 = d0 * d0 + d1 * d1 + d2 * d2 + 1e-12f;
    float R  = sqrtf(r2);
    float inv = 1.0f / R;

    float Ris[9], Rj[9];
#pragma unroll
    for (int k = 0; k < 9; k++) Ris[k] = orR[node * 9 + k];
#pragma unroll
    for (int k = 0; k < 9; k++) Rj[k]  = orR[nidx * 9 + k];

    float f[NF];
    f[0] = d0 * inv; f[1] = d1 * inv; f[2] = d2 * inv; f[3] = R;
#pragma unroll
    for (int j = 0; j < 3; j++) {
        f[4 + j] = f[0] * Ris[j] + f[1] * Ris[3 + j] + f[2] * Ris[6 + j];
        f[7 + j] = f[0] * Rj[j]  + f[1] * Rj[3 + j]  + f[2] * Rj[6 + j];
    }
#pragma unroll
    for (int j = 0; j < 3; j++)
#pragma unroll
        for (int k = 0; k < 3; k++)
            f[10 + j * 3 + k] = Ris[j] * Rj[k] + Ris[3 + j] * Rj[3 + k] + Ris[6 + j] * Rj[6 + k];

    {   // prior: warp shfl reduce
        float tp = 0.01f * inv;
        float tp2 = tp * tp, tp4 = tp2 * tp2, tp8 = tp4 * tp4;
        float pr = tp8 * tp4;
#pragma unroll
        for (int off = 16; off > 0; off >>= 1)
            pr += __shfl_xor_sync(0xffffffffu, pr, off);
        if (lane == 0) prw[wid] = pr;
    }

#pragma unroll
    for (int j2 = 0; j2 < 16; j2++) {
        float v0 = 0.f, v1 = 0.f;
        if (j2 < 9) { v0 = f[2 * j2]; v1 = f[2 * j2 + 1]; }
        else if (j2 == 9) { v0 = f[18]; }
        *(__nv_bfloat162*)(As + SW(t * 128 + j2 * 4)) = __floats2bfloat162_rn(v0, v1);
    }
    __syncthreads();

    float c[2][8][4];
    mma_layer<2>(As, Bs, wid, lane, c);

    // epilogue 0: relu(+b0) -> As (own warp rows only)
    {
        const int L = lane & 3;
        const int r0 = wid * 32 + (lane >> 2);
#pragma unroll
        for (int j = 0; j < 8; j++) {
            const int c0 = j * 8 + L * 2;
            float b0v = b0s[c0], b1v = b0s[c0 + 1];
            *(__nv_bfloat162*)(As + SW(r0 * 128 + c0 * 2)) =
                __floats2bfloat162_rn(fmaxf(c[0][j][0] + b0v, 0.f), fmaxf(c[0][j][1] + b1v, 0.f));
            *(__nv_bfloat162*)(As + SW((r0 + 8) * 128 + c0 * 2)) =
                __floats2bfloat162_rn(fmaxf(c[0][j][2] + b0v, 0.f), fmaxf(c[0][j][3] + b1v, 0.f));
            *(__nv_bfloat162*)(As + SW((r0 + 16) * 128 + c0 * 2)) =
                __floats2bfloat162_rn(fmaxf(c[1][j][0] + b0v, 0.f), fmaxf(c[1][j][1] + b1v, 0.f));
            *(__nv_bfloat162*)(As + SW((r0 + 24) * 128 + c0 * 2)) =
                __floats2bfloat162_rn(fmaxf(c[1][j][2] + b0v, 0.f), fmaxf(c[1][j][3] + b1v, 0.f));
        }
    }
    __syncthreads();

    for (int idx = t; idx < 2048; idx += 128) {
        int j = idx >> 5, k2 = idx & 31;
        *(__nv_bfloat162*)(Bs + SW(j * 128 + k2 * 4)) =
            __floats2bfloat162_rn(w1[j * 64 + 2 * k2], w1[j * 64 + 2 * k2 + 1]);
    }
    __syncthreads();

    mma_layer<4>(As, Bs, wid, lane, c);

    epi_store_stats(c, b1s, g_tbuf + ((size_t)cta * 128 + t) * 64, ps, pq, wid, lane);
    __syncthreads();

    if (t < 32) {
        float2 s = make_float2(0.f, 0.f), q = make_float2(0.f, 0.f);
#pragma unroll 8
        for (int r = 0; r < 32; r++) {
            float2 a = ps[r * 33 + t], qq = pq[r * 33 + t];
            s.x += a.x; s.y += a.y; q.x += qq.x; q.y += qq.y;
        }
        int c0 = (t >> 2) * 8 + (t & 3) * 2;
        atomicAdd(&g_sum1[c0],     (double)s.x);
        atomicAdd(&g_sum1[c0 + 1], (double)s.y);
        atomicAdd(&g_sq1[c0],      (double)q.x);
        atomicAdd(&g_sq1[c0 + 1],  (double)q.y);
    }
    if (t == 0)
        atomicAdd(&g_U0[b], (double)((prw[0] + prw[1]) + (prw[2] + prw[3])));
}

// ---------------- stage 2 ----------------
__global__ __launch_bounds__(128, 4)
void k_edge2(const float* __restrict__ g1, const float* __restrict__ be1,
             const float* __restrict__ w2, const float* __restrict__ b2)
{
    __shared__ __align__(128) unsigned char As[16384];
    __shared__ __align__(128) unsigned char Bs[8192];
    __shared__ float2 ps[32 * 33], pq[32 * 33];
    __shared__ float b2s[64], sc[64], sh[64];

    const int t = threadIdx.x, wid = t >> 5, lane = t & 31;
    const int cta = blockIdx.x;

    uint4 rv[8];
    {
        const uint4* rp = (const uint4*)(g_tbuf + ((size_t)cta * 128 + t) * 64);
#pragma unroll
        for (int q = 0; q < 8; q++) rv[q] = rp[q];
    }
    if (t < 64) {
        b2s[t] = b2[t];
        double mean = g_sum1[t] / (double)NE;
        double var  = g_sq1[t] / (double)NE - mean * mean;
        float istd  = rsqrtf((float)var + 1e-5f);
        float scale = g1[t] * istd;
        sc[t] = scale;
        sh[t] = be1[t] - (float)mean * scale;
    }
    for (int idx = t; idx < 2048; idx += 128) {
        int j = idx >> 5, k2 = idx & 31;
        *(__nv_bfloat162*)(Bs + SW(j * 128 + k2 * 4)) =
            __floats2bfloat162_rn(w2[j * 64 + 2 * k2], w2[j * 64 + 2 * k2 + 1]);
    }
    __syncthreads();

    consume_to_As(rv, As, sc, sh, wid, lane);
    __syncwarp();

    float c[2][8][4];
    mma_layer<4>(As, Bs, wid, lane, c);

    epi_store_stats(c, b2s, g_tbuf + ((size_t)cta * 128 + t) * 64, ps, pq, wid, lane);
    __syncthreads();

    if (t < 32) {
        float2 s = make_float2(0.f, 0.f), q = make_float2(0.f, 0.f);
#pragma unroll 8
        for (int r = 0; r < 32; r++) {
            float2 a = ps[r * 33 + t], qq = pq[r * 33 + t];
            s.x += a.x; s.y += a.y; q.x += qq.x; q.y += qq.y;
        }
        int c0 = (t >> 2) * 8 + (t & 3) * 2;
        atomicAdd(&g_sum2[c0],     (double)s.x);
        atomicAdd(&g_sum2[c0 + 1], (double)s.y);
        atomicAdd(&g_sq2[c0],      (double)q.x);
        atomicAdd(&g_sq2[c0 + 1],  (double)q.y);
    }
}

// ---------------- stage 3 ----------------
__global__ __launch_bounds__(128, 4)
void k_edge3(const float* __restrict__ g2, const float* __restrict__ be2,
             const float* __restrict__ w3, const float* __restrict__ b3)
{
    __shared__ __align__(128) unsigned char As[16384];
    __shared__ __align__(128) unsigned char Bs[8192];
    __shared__ float2 ps[32 * 33];
    __shared__ float b3s[64], sc[64], sh[64];

    const int t = threadIdx.x, wid = t >> 5, lane = t & 31;
    const int cta = blockIdx.x;
    const int node0 = cta * 2;

    uint4 rv[8];
    {
        const uint4* rp = (const uint4*)(g_tbuf + ((size_t)cta * 128 + t) * 64);
#pragma unroll
        for (int q = 0; q < 8; q++) rv[q] = rp[q];
    }
    if (t < 64) {
        b3s[t] = b3[t];
        double mean = g_sum2[t] / (double)NE;
        double var  = g_sq2[t] / (double)NE - mean * mean;
        float istd  = rsqrtf((float)var + 1e-5f);
        float scale = g2[t] * istd;
        sc[t] = scale;
        sh[t] = be2[t] - (float)mean * scale;
    }
    for (int idx = t; idx < 2048; idx += 128) {
        int j = idx >> 5, k2 = idx & 31;
        *(__nv_bfloat162*)(Bs + SW(j * 128 + k2 * 4)) =
            __floats2bfloat162_rn(w3[j * 64 + 2 * k2], w3[j * 64 + 2 * k2 + 1]);
    }
    __syncthreads();

    consume_to_As(rv, As, sc, sh, wid, lane);
    __syncwarp();

    float c[2][8][4];
    mma_layer<4>(As, Bs, wid, lane, c);

    // partial column sums (pooled output stays fp32)
    {
        const int rcls = wid * 8 + (lane >> 2);
        const int L = lane & 3;
#pragma unroll
        for (int j = 0; j < 8; j++) {
            float sx = (c[0][j][0] + c[0][j][2]) + (c[1][j][0] + c[1][j][2]);
            float sy = (c[0][j][1] + c[0][j][3]) + (c[1][j][1] + c[1][j][3]);
            ps[rcls * 33 + j * 4 + L] = make_float2(sx, sy);
        }
    }
    __syncthreads();

    {
        int nodesel = t >> 6;            // 0 or 1
        int cidx = t & 63;               // output column
        int p = (cidx >> 3) * 4 + ((cidx & 7) >> 1);
        int comp = cidx & 1;
        float s = 0.f;
        int rbase = nodesel * 16;
#pragma unroll 8
        for (int r = 0; r < 16; r++) {
            float2 a = ps[(rbase + r) * 33 + p];
            s += comp ? a.y : a.x;
        }
        g_pooled[(node0 + nodesel) * HH + cidx] = s * (1.0f / NNB) + b3s[cidx];
    }
}

// ---------------- per-feature max over particles ----------------
__global__ __launch_bounds__(1024) void k_colmax(int insel)
{
    const float* z = selz(insel);
    const int b = blockIdx.x;
    const int t = threadIdx.x;
    const int f = t & 63, g = t >> 6;
    float mx = -INFINITY;
    for (int n = g; n < NP; n += 16)
        mx = fmaxf(mx, z[((size_t)b * NP + n) * HH + f]);
    __shared__ float red[1024];
    red[t] = mx;
    __syncthreads();
    if (g == 0) {
        float v = red[f];
#pragma unroll
        for (int r = 1; r < 16; r++) v = fmaxf(v, red[r * 64 + f]);
        g_colmax[b * HH + f] = v;
    }
}

// ---------------- PermEqui1_max (BBx16 grid, 128 threads, 125 rows/CTA) ----------------
__global__ __launch_bounds__(128) void k_pe(int insel, int outsel,
    const float* __restrict__ w, const float* __restrict__ bias)
{
    __shared__ float ws[HH * HH], cf[HH], cms[HH];
    const int bx = blockIdx.x;
    const int b  = bx >> 4;
    const int rb = bx & 15;
    const int t  = threadIdx.x;
    const float* zin = selz(insel);
    float* zout = (outsel == 1) ? g_zA : g_zB;

    for (int i = t; i < HH * HH; i += 128) ws[i] = w[i];
    if (t < HH) cms[t] = g_colmax[b * HH + t];
    __syncthreads();

    if (t < HH) {
        float a0 = bias[t], a1 = 0.f, a2 = 0.f, a3 = 0.f;
#pragma unroll
        for (int h = 0; h < HH; h += 4) {
            a0 -= cms[h]     * ws[t * 64 + h];
            a1 -= cms[h + 1] * ws[t * 64 + h + 1];
            a2 -= cms[h + 2] * ws[t * 64 + h + 2];
            a3 -= cms[h + 3] * ws[t * 64 + h + 3];
        }
        cf[t] = (a0 + a1) + (a2 + a3);
    }
    __syncthreads();

    const int n = rb * 125 + t;
    if (t < 125) {
        const float* zr = &zin[((size_t)b * NP + n) * HH];
        float z[HH];
#pragma unroll
        for (int h = 0; h < HH; h++) z[h] = zr[h];
        float* orow = &zout[((size_t)b * NP + n) * HH];
#pragma unroll 4
        for (int fj = 0; fj < HH; fj++) {
            float a0 = cf[fj], a1 = 0.f, a2 = 0.f, a3 = 0.f;
#pragma unroll
            for (int h = 0; h < HH; h += 4) {
                a0 += z[h]     * ws[fj * 64 + h];
                a1 += z[h + 1] * ws[fj * 64 + h + 1];
                a2 += z[h + 2] * ws[fj * 64 + h + 2];
                a3 += z[h + 3] * ws[fj * 64 + h + 3];
            }
            orow[fj] = tanhf((a0 + a1) + (a2 + a3));
        }
    }
}

// ---------------- head ----------------
__global__ __launch_bounds__(64) void k_head(
    const float* __restrict__ r1w, const float* __restrict__ r1b,
    const float* __restrict__ r2w, const float* __restrict__ r2b,
    float* __restrict__ out)
{
    const int b = blockIdx.x;
    const int f = threadIdx.x;
    __shared__ float s[HH], tv[HH];

    s[f] = g_colmax[b * HH + f];
    __syncthreads();

    float a = r1b[f];
#pragma unroll
    for (int h = 0; h < HH; h++) a += s[h] * r1w[f * 64 + h];
    tv[f] = tanhf(a);
    __syncthreads();

    if (f == 0) {
        float e = r2b[0];
        for (int h = 0; h < HH; h++) e += tv[h] * r2w[h];
        out[b] = e + (float)g_U0[b];
    }
}

// ---------------- launcher ----------------
extern "C" void kernel_launch(void* const* d_in, const int* in_sizes, int n_in,
                              void* d_out, int out_size)
{
    const float* pos = (const float*)d_in[0];
    const float* orR = (const float*)d_in[1];
    const int*   nbr = (const int*)  d_in[2];
    const float* w0  = (const float*)d_in[3];
    const float* b0  = (const float*)d_in[4];
    const float* w1  = (const float*)d_in[5];
    const float* b1  = (const float*)d_in[6];
    const float* g1  = (const float*)d_in[7];
    const float* be1 = (const float*)d_in[8];
    const float* w2  = (const float*)d_in[9];
    const float* b2  = (const float*)d_in[10];
    const float* g2  = (const float*)d_in[11];
    const float* be2 = (const float*)d_in[12];
    const float* w3  = (const float*)d_in[13];
    const float* b3  = (const float*)d_in[14];
    const float* p1w = (const float*)d_in[15];
    const float* p1b = (const float*)d_in[16];
    const float* p2w = (const float*)d_in[17];
    const float* p2b = (const float*)d_in[18];
    const float* p3w = (const float*)d_in[19];
    const float* p3b = (const float*)d_in[20];
    const float* r1w = (const float*)d_in[21];
    const float* r1b = (const float*)d_in[22];
    const float* r2w = (const float*)d_in[23];
    const float* r2b = (const float*)d_in[24];
    float* out = (float*)d_out;

    k_zero <<<1, 64>>>();
    k_edge1<<<NCTA, 128>>>(pos, orR, nbr, w0, b0, w1, b1);
    k_edge2<<<NCTA, 128>>>(g1, be1, w2, b2);
    k_edge3<<<NCTA, 128>>>(g2, be2, w3, b3);
    k_colmax<<<BB, 1024>>>(0);
    k_pe   <<<BB * 16, 128>>>(0, 1, p1w, p1b);
    k_colmax<<<BB, 1024>>>(1);
    k_pe   <<<BB * 16, 128>>>(1, 2, p2w, p2b);
    k_colmax<<<BB, 1024>>>(2);
    k_pe   <<<BB * 16, 128>>>(2, 1, p3w, p3b);
    k_colmax<<<BB, 1024>>>(1);
    k_head <<<BB, 64>>>(r1w, r1b, r2w, r2b, out);
}

// round 13
// speedup vs baseline: 1.8509x; 1.7245x over previous
#include <cuda_runtime.h>
#include <cuda_fp16.h>
#include <cuda_bf16.h>
#include <math.h>
#include <stdint.h>

#define BB   8
#define NP   2000
#define NNB  64
#define NF   19
#define HH   64
#define NNODE (BB*NP)          // 16000
#define NE   (BB*NP*NNB)       // 1024000
#define NCTA (NNODE/2)         // 8000 tiles (2 nodes / 128 edges each)
#define EDGE_GRID 592          // 148 SMs x 4 resident CTAs

// ---------------- device scratch ----------------
// fragment-native layout: [tile][tid 0..127][32 x half2]
__device__ __half g_tbuf[(size_t)NE * HH];
__device__ float  g_pooled[NNODE * HH];
__device__ float  g_zA[NNODE * HH];
__device__ float  g_zB[NNODE * HH];
__device__ unsigned g_cm[4][BB * HH];     // encoded col-max: 0=pooled,1=pe1,2=pe2,3=pe3
__device__ double g_sum1[HH], g_sq1[HH], g_sum2[HH], g_sq2[HH];
__device__ double g_U0[BB];

__device__ __forceinline__ const float* selz(int w) {
    return w == 0 ? g_pooled : (w == 1 ? g_zA : g_zB);
}

// monotonic float<->uint for atomicMax
__device__ __forceinline__ unsigned enc_f(float x) {
    unsigned u = __float_as_uint(x);
    return (u & 0x80000000u) ? ~u : (u | 0x80000000u);
}
__device__ __forceinline__ float dec_f(unsigned k) {
    return __uint_as_float((k & 0x80000000u) ? (k & 0x7FFFFFFFu) : ~k);
}

__device__ __forceinline__ uint32_t smem_u32(const void* p) {
    uint32_t a;
    asm("{ .reg .u64 t; cvta.to.shared.u64 t, %1; cvt.u32.u64 %0, t; }" : "=r"(a) : "l"(p));
    return a;
}

#define SW(o) ((o) ^ (((o) >> 3) & 0x70))

// ---- warp-level bf16 MMA ----
#define MMA16816(c, a, br0, br1) \
    asm volatile("mma.sync.aligned.m16n8k16.row.col.f32.bf16.bf16.f32 " \
                 "{%0,%1,%2,%3}, {%4,%5,%6,%7}, {%8,%9}, {%0,%1,%2,%3};" \
                 : "+f"((c)[0]), "+f"((c)[1]), "+f"((c)[2]), "+f"((c)[3]) \
                 : "r"((a)[0]), "r"((a)[1]), "r"((a)[2]), "r"((a)[3]), \
                   "r"(br0), "r"(br1))

__device__ __forceinline__ void ldmA(uint32_t a[4], const unsigned char* As,
                                     int m0, int k0, int lane) {
    int row = m0 + (lane & 7) + ((lane & 8) ? 8 : 0);
    int kc  = k0 + ((lane & 16) ? 8 : 0);
    uint32_t addr = smem_u32(As + SW(row * 128 + kc * 2));
    asm volatile("ldmatrix.sync.aligned.m8n8.x4.shared.b16 {%0,%1,%2,%3}, [%4];"
                 : "=r"(a[0]), "=r"(a[1]), "=r"(a[2]), "=r"(a[3]) : "r"(addr));
}

__device__ __forceinline__ void ldmB(uint32_t b[4], const unsigned char* Bs,
                                     int n0, int k0, int lane) {
    int row = n0 + (lane & 7) + ((lane & 16) ? 8 : 0);
    int kc  = k0 + ((lane & 8) ? 8 : 0);
    uint32_t addr = smem_u32(Bs + SW(row * 128 + kc * 2));
    asm volatile("ldmatrix.sync.aligned.m8n8.x4.shared.b16 {%0,%1,%2,%3}, [%4];"
                 : "=r"(b[0]), "=r"(b[1]), "=r"(b[2]), "=r"(b[3]) : "r"(addr));
}

template <int KS>
__device__ __forceinline__ void mma_layer(const unsigned char* As, const unsigned char* Bs,
                                          int wid, int lane, float c[2][8][4]) {
#pragma unroll
    for (int i = 0; i < 2; i++)
#pragma unroll
        for (int j = 0; j < 8; j++)
#pragma unroll
            for (int q = 0; q < 4; q++) c[i][j][q] = 0.f;
#pragma unroll
    for (int ks = 0; ks < KS; ks++) {
        int k0 = ks * 16;
        uint32_t a0[4], a1[4];
        ldmA(a0, As, wid * 32, k0, lane);
        ldmA(a1, As, wid * 32 + 16, k0, lane);
#pragma unroll
        for (int jt = 0; jt < 4; jt++) {
            uint32_t b[4];
            ldmB(b, Bs, jt * 16, k0, lane);
            MMA16816(c[0][jt * 2],     a0, b[0], b[1]);
            MMA16816(c[0][jt * 2 + 1], a0, b[2], b[3]);
            MMA16816(c[1][jt * 2],     a1, b[0], b[1]);
            MMA16816(c[1][jt * 2 + 1], a1, b[2], b[3]);
        }
    }
}

// stage weights [64][64] row-major into swizzled 8KB B tile
__device__ __forceinline__ void stage_w(const float* __restrict__ w,
                                        unsigned char* Bs, int t) {
    for (int idx = t; idx < 2048; idx += 128) {
        int j = idx >> 5, k2 = idx & 31;
        *(__nv_bfloat162*)(Bs + SW(j * 128 + k2 * 4)) =
            __floats2bfloat162_rn(w[j * 64 + 2 * k2], w[j * 64 + 2 * k2 + 1]);
    }
}

// ---------------- zero/init accumulators ----------------
__global__ void k_zero() {
    int t = threadIdx.x;
    if (t < HH) { g_sum1[t] = 0.0; g_sq1[t] = 0.0; g_sum2[t] = 0.0; g_sq2[t] = 0.0; }
    if (t < BB) g_U0[t] = 0.0;
    for (int i = t; i < 4 * BB * HH; i += 512) g_cm[i >> 9][i & 511] = 0u;
}

// epilogue (smem-accumulating variant, used by edge2)
__device__ __forceinline__ void epi_store_stats(
    float c[2][8][4], const float* bias, __half* tbase,
    float2* ps, float2* pq, int wid, int lane)
{
    const int rcls = wid * 8 + (lane >> 2);
    const int L = lane & 3;
    __half2 o[32];
#pragma unroll
    for (int j = 0; j < 8; j++) {
        const int c0 = j * 8 + L * 2;
        float b0v = bias[c0], b1v = bias[c0 + 1];
        __half2 h0 = __floats2half2_rn(c[0][j][0] + b0v, c[0][j][1] + b1v);
        __half2 h1 = __floats2half2_rn(c[0][j][2] + b0v, c[0][j][3] + b1v);
        __half2 h2 = __floats2half2_rn(c[1][j][0] + b0v, c[1][j][1] + b1v);
        __half2 h3 = __floats2half2_rn(c[1][j][2] + b0v, c[1][j][3] + b1v);
        o[j * 2]          = h0;
        o[j * 2 + 1]      = h1;
        o[16 + j * 2]     = h2;
        o[16 + j * 2 + 1] = h3;
        float2 v0 = __half22float2(h0), v1 = __half22float2(h1);
        float2 v2 = __half22float2(h2), v3 = __half22float2(h3);
        float sx = (v0.x + v1.x) + (v2.x + v3.x);
        float sy = (v0.y + v1.y) + (v2.y + v3.y);
        float qx = (v0.x * v0.x + v1.x * v1.x) + (v2.x * v2.x + v3.x * v3.x);
        float qy = (v0.y * v0.y + v1.y * v1.y) + (v2.y * v2.y + v3.y * v3.y);
        int slot = rcls * 33 + j * 4 + L;
        float2 a = ps[slot]; a.x += sx; a.y += sy; ps[slot] = a;
        float2 qv = pq[slot]; qv.x += qx; qv.y += qy; pq[slot] = qv;
    }
#pragma unroll
    for (int q = 0; q < 8; q++) *(uint4*)(tbase + 8 * q) = ((uint4*)o)[q];
}

// consumer: fragment-native row -> BN+relu -> As (own warp rows only)
__device__ __forceinline__ void consume_to_As(
    const uint4 rv[8], unsigned char* As, const float* sc, const float* sh,
    int wid, int lane)
{
    const int rbase = wid * 32 + (lane >> 2);
    const int c0b = (lane & 3) * 2;
#pragma unroll
    for (int s2 = 0; s2 < 8; s2++) {
        const __half2* hp = (const __half2*)&rv[s2];
#pragma unroll
        for (int u = 0; u < 4; u++) {
            int s = s2 * 4 + u;
            int i = s >> 4, j = (s >> 1) & 7, p = s & 1;
            int row = rbase + i * 16 + p * 8;
            int c0 = j * 8 + c0b;
            float2 v = __half22float2(hp[u]);
            float h0 = fmaxf(v.x * sc[c0]     + sh[c0],     0.f);
            float h1 = fmaxf(v.y * sc[c0 + 1] + sh[c0 + 1], 0.f);
            *(__nv_bfloat162*)(As + SW(row * 128 + c0 * 2)) = __floats2bfloat162_rn(h0, h1);
        }
    }
}

// ---------------- stage 1 (persistent, register stats accumulators) ----------------
__global__ __launch_bounds__(128, 4)
void k_edge1(const float* __restrict__ pos, const float* __restrict__ orR,
             const int* __restrict__ nbr,
             const float* __restrict__ w0, const float* __restrict__ b0,
             const float* __restrict__ w1, const float* __restrict__ b1)
{
    __shared__ __align__(128) unsigned char As[16384];
    __shared__ __align__(128) unsigned char Bs0[8192], Bs1[8192];
    __shared__ float b0s[64], b1s[64], prb[4][8];

    const int t = threadIdx.x, wid = t >> 5, lane = t & 31;
    const int L = lane & 3;
    const int rcls = wid * 8 + (lane >> 2);

    if (t < 64) { b0s[t] = b0[t]; b1s[t] = b1[t]; }
    if (lane < 8) prb[wid][lane] = 0.f;

    float2 accS[8], accQ[8];
#pragma unroll
    for (int j = 0; j < 8; j++) {
        accS[j] = make_float2(0.f, 0.f);
        accQ[j] = make_float2(0.f, 0.f);
    }

    // stage w0 (zero-padded to K=32) and w1, once per CTA
    for (int idx = t; idx < 1024; idx += 128) {
        int j = idx >> 4, k2 = idx & 15;
        int c0 = 2 * k2, c1 = c0 + 1;
        float v0 = (c0 < NF) ? w0[j * NF + c0] : 0.f;
        float v1 = (c1 < NF) ? w0[j * NF + c1] : 0.f;
        *(__nv_bfloat162*)(Bs0 + SW(j * 128 + k2 * 4)) = __floats2bfloat162_rn(v0, v1);
    }
    stage_w(w1, Bs1, t);
    __syncthreads();

    for (int tile = blockIdx.x; tile < NCTA; tile += EDGE_GRID) {
        const int node0 = tile * 2;
        const int b = node0 / NP;
        const int node = node0 + (t >> 6);
        const int m    = t & 63;
        const int jn   = nbr[node * NNB + m];
        const int nidx = b * NP + jn;

        float d0 = pos[nidx * 3 + 0] - pos[node * 3 + 0]; d0 -= rintf(d0);
        float d1 = pos[nidx * 3 + 1] - pos[node * 3 + 1]; d1 -= rintf(d1);
        float d2 = pos[nidx * 3 + 2] - pos[node * 3 + 2]; d2 -= rintf(d2);
        float r2 = d0 * d0 + d1 * d1 + d2 * d2 + 1e-12f;
        float R  = sqrtf(r2);
        float inv = 1.0f / R;

        float Ris[9], Rj[9];
#pragma unroll
        for (int k = 0; k < 9; k++) Ris[k] = orR[node * 9 + k];
#pragma unroll
        for (int k = 0; k < 9; k++) Rj[k]  = orR[nidx * 9 + k];

        float f[NF];
        f[0] = d0 * inv; f[1] = d1 * inv; f[2] = d2 * inv; f[3] = R;
#pragma unroll
        for (int j = 0; j < 3; j++) {
            f[4 + j] = f[0] * Ris[j] + f[1] * Ris[3 + j] + f[2] * Ris[6 + j];
            f[7 + j] = f[0] * Rj[j]  + f[1] * Rj[3 + j]  + f[2] * Rj[6 + j];
        }
#pragma unroll
        for (int j = 0; j < 3; j++)
#pragma unroll
            for (int k = 0; k < 3; k++)
                f[10 + j * 3 + k] = Ris[j] * Rj[k] + Ris[3 + j] * Rj[3 + k] + Ris[6 + j] * Rj[6 + k];

        {   // prior: warp reduce, accumulate per-warp per-batch (exclusive slots)
            float tp = 0.01f * inv;
            float tp2 = tp * tp, tp4 = tp2 * tp2, tp8 = tp4 * tp4;
            float pr = tp8 * tp4;
#pragma unroll
            for (int off = 16; off > 0; off >>= 1)
                pr += __shfl_xor_sync(0xffffffffu, pr, off);
            if (lane == 0) prb[wid][b] += pr;
        }

#pragma unroll
        for (int j2 = 0; j2 < 16; j2++) {
            float v0 = 0.f, v1 = 0.f;
            if (j2 < 9) { v0 = f[2 * j2]; v1 = f[2 * j2 + 1]; }
            else if (j2 == 9) { v0 = f[18]; }
            *(__nv_bfloat162*)(As + SW(t * 128 + j2 * 4)) = __floats2bfloat162_rn(v0, v1);
        }
        __syncwarp();

        float c[2][8][4];
        mma_layer<2>(As, Bs0, wid, lane, c);

        // epilogue 0: relu(+b0) -> As (own warp rows)
        {
            const int r0 = wid * 32 + (lane >> 2);
#pragma unroll
            for (int j = 0; j < 8; j++) {
                const int c0 = j * 8 + L * 2;
                float b0v = b0s[c0], b1v = b0s[c0 + 1];
                *(__nv_bfloat162*)(As + SW(r0 * 128 + c0 * 2)) =
                    __floats2bfloat162_rn(fmaxf(c[0][j][0] + b0v, 0.f), fmaxf(c[0][j][1] + b1v, 0.f));
                *(__nv_bfloat162*)(As + SW((r0 + 8) * 128 + c0 * 2)) =
                    __floats2bfloat162_rn(fmaxf(c[0][j][2] + b0v, 0.f), fmaxf(c[0][j][3] + b1v, 0.f));
                *(__nv_bfloat162*)(As + SW((r0 + 16) * 128 + c0 * 2)) =
                    __floats2bfloat162_rn(fmaxf(c[1][j][0] + b0v, 0.f), fmaxf(c[1][j][1] + b1v, 0.f));
                *(__nv_bfloat162*)(As + SW((r0 + 24) * 128 + c0 * 2)) =
                    __floats2bfloat162_rn(fmaxf(c[1][j][2] + b0v, 0.f), fmaxf(c[1][j][3] + b1v, 0.f));
            }
        }
        __syncwarp();

        mma_layer<4>(As, Bs1, wid, lane, c);

        // epilogue 1: +b1, round fp16, store coalesced, accumulate stats in regs
        {
            __half2 o[32];
#pragma unroll
            for (int j = 0; j < 8; j++) {
                const int c0 = j * 8 + L * 2;
                float b0v = b1s[c0], b1v = b1s[c0 + 1];
                __half2 h0 = __floats2half2_rn(c[0][j][0] + b0v, c[0][j][1] + b1v);
                __half2 h1 = __floats2half2_rn(c[0][j][2] + b0v, c[0][j][3] + b1v);
                __half2 h2 = __floats2half2_rn(c[1][j][0] + b0v, c[1][j][1] + b1v);
                __half2 h3 = __floats2half2_rn(c[1][j][2] + b0v, c[1][j][3] + b1v);
                o[j * 2]          = h0;
                o[j * 2 + 1]      = h1;
                o[16 + j * 2]     = h2;
                o[16 + j * 2 + 1] = h3;
                float2 v0 = __half22float2(h0), v1 = __half22float2(h1);
                float2 v2 = __half22float2(h2), v3 = __half22float2(h3);
                accS[j].x += (v0.x + v1.x) + (v2.x + v3.x);
                accS[j].y += (v0.y + v1.y) + (v2.y + v3.y);
                accQ[j].x += (v0.x * v0.x + v1.x * v1.x) + (v2.x * v2.x + v3.x * v3.x);
                accQ[j].y += (v0.y * v0.y + v1.y * v1.y) + (v2.y * v2.y + v3.y * v3.y);
            }
            __half* tbase = g_tbuf + ((size_t)tile * 128 + t) * 64;
#pragma unroll
            for (int q = 0; q < 8; q++) *(uint4*)(tbase + 8 * q) = ((uint4*)o)[q];
        }
    }

    // final stats reduction: overlay As (now dead) as two stride-32 float2 arrays
    __syncthreads();
    {
        float2* ps2 = (float2*)As;               // 8192 B
        float2* pq2 = (float2*)(As + 8192);      // 8192 B
#pragma unroll
        for (int j = 0; j < 8; j++) {
            ps2[rcls * 32 + j * 4 + L] = accS[j];
            pq2[rcls * 32 + j * 4 + L] = accQ[j];
        }
    }
    __syncthreads();
    if (t < 32) {
        const float2* ps2 = (const float2*)As;
        const float2* pq2 = (const float2*)(As + 8192);
        float2 s = make_float2(0.f, 0.f), q = make_float2(0.f, 0.f);
#pragma unroll 8
        for (int r = 0; r < 32; r++) {
            float2 a = ps2[r * 32 + t], qq = pq2[r * 32 + t];
            s.x += a.x; s.y += a.y; q.x += qq.x; q.y += qq.y;
        }
        int c0 = (t >> 2) * 8 + (t & 3) * 2;
        atomicAdd(&g_sum1[c0],     (double)s.x);
        atomicAdd(&g_sum1[c0 + 1], (double)s.y);
        atomicAdd(&g_sq1[c0],      (double)q.x);
        atomicAdd(&g_sq1[c0 + 1],  (double)q.y);
    }
    if (t < 8) {
        float p = (prb[0][t] + prb[1][t]) + (prb[2][t] + prb[3][t]);
        if (p != 0.f) atomicAdd(&g_U0[t], (double)p);
    }
}

// ---------------- stage 2 (persistent) ----------------
__global__ __launch_bounds__(128, 4)
void k_edge2(const float* __restrict__ g1, const float* __restrict__ be1,
             const float* __restrict__ w2, const float* __restrict__ b2)
{
    __shared__ __align__(128) unsigned char As[16384];
    __shared__ __align__(128) unsigned char Bs[8192];
    __shared__ float2 ps[32 * 33], pq[32 * 33];
    __shared__ float b2s[64], sc[64], sh[64];

    const int t = threadIdx.x, wid = t >> 5, lane = t & 31;

    if (t < 64) {
        b2s[t] = b2[t];
        double mean = g_sum1[t] / (double)NE;
        double var  = g_sq1[t] / (double)NE - mean * mean;
        float istd  = rsqrtf((float)var + 1e-5f);
        float scale = g1[t] * istd;
        sc[t] = scale;
        sh[t] = be1[t] - (float)mean * scale;
    }
    {
        const int rcls = wid * 8 + (lane >> 2), L = lane & 3;
#pragma unroll
        for (int j = 0; j < 8; j++) {
            ps[rcls * 33 + j * 4 + L] = make_float2(0.f, 0.f);
            pq[rcls * 33 + j * 4 + L] = make_float2(0.f, 0.f);
        }
    }
    stage_w(w2, Bs, t);
    __syncthreads();

    for (int tile = blockIdx.x; tile < NCTA; tile += EDGE_GRID) {
        uint4 rv[8];
        const uint4* rp = (const uint4*)(g_tbuf + ((size_t)tile * 128 + t) * 64);
#pragma unroll
        for (int q = 0; q < 8; q++) rv[q] = rp[q];

        consume_to_As(rv, As, sc, sh, wid, lane);
        __syncwarp();

        float c[2][8][4];
        mma_layer<4>(As, Bs, wid, lane, c);
        epi_store_stats(c, b2s, g_tbuf + ((size_t)tile * 128 + t) * 64, ps, pq, wid, lane);
    }

    __syncthreads();
    if (t < 32) {
        float2 s = make_float2(0.f, 0.f), q = make_float2(0.f, 0.f);
#pragma unroll 8
        for (int r = 0; r < 32; r++) {
            float2 a = ps[r * 33 + t], qq = pq[r * 33 + t];
            s.x += a.x; s.y += a.y; q.x += qq.x; q.y += qq.y;
        }
        int c0 = (t >> 2) * 8 + (t & 3) * 2;
        atomicAdd(&g_sum2[c0],     (double)s.x);
        atomicAdd(&g_sum2[c0 + 1], (double)s.y);
        atomicAdd(&g_sq2[c0],      (double)q.x);
        atomicAdd(&g_sq2[c0 + 1],  (double)q.y);
    }
}

// ---------------- stage 3 (persistent) + fused colmax of pooled ----------------
__global__ __launch_bounds__(128, 4)
void k_edge3(const float* __restrict__ g2, const float* __restrict__ be2,
             const float* __restrict__ w3, const float* __restrict__ b3)
{
    __shared__ __align__(128) unsigned char As[16384];
    __shared__ __align__(128) unsigned char Bs[8192];
    __shared__ float2 ps[32 * 33];
    __shared__ float pm[128];
    __shared__ float b3s[64], sc[64], sh[64];

    const int t = threadIdx.x, wid = t >> 5, lane = t & 31;

    if (t < 64) {
        b3s[t] = b3[t];
        double mean = g_sum2[t] / (double)NE;
        double var  = g_sq2[t] / (double)NE - mean * mean;
        float istd  = rsqrtf((float)var + 1e-5f);
        float scale = g2[t] * istd;
        sc[t] = scale;
        sh[t] = be2[t] - (float)mean * scale;
    }
    stage_w(w3, Bs, t);
    __syncthreads();

    for (int tile = blockIdx.x; tile < NCTA; tile += EDGE_GRID) {
        const int node0 = tile * 2;
        const int b = node0 / NP;

        uint4 rv[8];
        const uint4* rp = (const uint4*)(g_tbuf + ((size_t)tile * 128 + t) * 64);
#pragma unroll
        for (int q = 0; q < 8; q++) rv[q] = rp[q];

        consume_to_As(rv, As, sc, sh, wid, lane);
        __syncwarp();

        float c[2][8][4];
        mma_layer<4>(As, Bs, wid, lane, c);

        {
            const int rcls = wid * 8 + (lane >> 2);
            const int L = lane & 3;
#pragma unroll
            for (int j = 0; j < 8; j++) {
                float sx = (c[0][j][0] + c[0][j][2]) + (c[1][j][0] + c[1][j][2]);
                float sy = (c[0][j][1] + c[0][j][3]) + (c[1][j][1] + c[1][j][3]);
                ps[rcls * 33 + j * 4 + L] = make_float2(sx, sy);
            }
        }
        __syncthreads();

        {
            int nodesel = t >> 6;
            int cidx = t & 63;
            int p = (cidx >> 3) * 4 + ((cidx & 7) >> 1);
            int comp = cidx & 1;
            float s = 0.f;
            int rbase = nodesel * 16;
#pragma unroll 8
            for (int r = 0; r < 16; r++) {
                float2 a = ps[(rbase + r) * 33 + p];
                s += comp ? a.y : a.x;
            }
            s = s * (1.0f / NNB) + b3s[cidx];
            g_pooled[(node0 + nodesel) * HH + cidx] = s;
            pm[t] = s;
        }
        __syncthreads();
        if (t < 64)
            atomicMax(&g_cm[0][b * HH + t], enc_f(fmaxf(pm[t], pm[t + 64])));
    }
}

// ---------------- PermEqui1_max + fused output colmax ----------------
__global__ __launch_bounds__(128) void k_pe(int insel, int cmin, int cmout, int outsel,
    const float* __restrict__ w, const float* __restrict__ bias)
{
    __shared__ float ws[HH * HH], cf[HH], cms[HH];
    __shared__ float wm[HH * 4];
    const int bx = blockIdx.x;
    const int b  = bx >> 4;
    const int rb = bx & 15;
    const int t  = threadIdx.x;
    const int wid = t >> 5, lane = t & 31;
    const float* zin = selz(insel);
    float* zout = (outsel == 1) ? g_zA : ((outsel == 2) ? g_zB : 0);

    for (int i = t; i < HH * HH; i += 128) ws[i] = w[i];
    if (t < HH) cms[t] = dec_f(g_cm[cmin][b * HH + t]);
    __syncthreads();

    if (t < HH) {
        float a0 = bias[t], a1 = 0.f, a2 = 0.f, a3 = 0.f;
#pragma unroll
        for (int h = 0; h < HH; h += 4) {
            a0 -= cms[h]     * ws[t * 64 + h];
            a1 -= cms[h + 1] * ws[t * 64 + h + 1];
            a2 -= cms[h + 2] * ws[t * 64 + h + 2];
            a3 -= cms[h + 3] * ws[t * 64 + h + 3];
        }
        cf[t] = (a0 + a1) + (a2 + a3);
    }
    __syncthreads();

    const int n = rb * 125 + t;
    const bool valid = (t < 125);
    float z[HH];
    const float* zr = &zin[((size_t)b * NP + (valid ? n : 0)) * HH];
#pragma unroll
    for (int h = 0; h < HH; h++) z[h] = zr[h];
    float* orow = zout ? &zout[((size_t)b * NP + n) * HH] : 0;

#pragma unroll 4
    for (int fj = 0; fj < HH; fj++) {
        float a0 = cf[fj], a1 = 0.f, a2 = 0.f, a3 = 0.f;
#pragma unroll
        for (int h = 0; h < HH; h += 4) {
            a0 += z[h]     * ws[fj * 64 + h];
            a1 += z[h + 1] * ws[fj * 64 + h + 1];
            a2 += z[h + 2] * ws[fj * 64 + h + 2];
            a3 += z[h + 3] * ws[fj * 64 + h + 3];
        }
        float v = tanhf((a0 + a1) + (a2 + a3));
        if (valid && orow) orow[fj] = v;
        float mv = valid ? v : -INFINITY;
#pragma unroll
        for (int off = 16; off > 0; off >>= 1)
            mv = fmaxf(mv, __shfl_xor_sync(0xffffffffu, mv, off));
        if (lane == 0) wm[fj * 4 + wid] = mv;
    }
    __syncthreads();
    if (t < HH) {
        float m = fmaxf(fmaxf(wm[t * 4], wm[t * 4 + 1]), fmaxf(wm[t * 4 + 2], wm[t * 4 + 3]));
        atomicMax(&g_cm[cmout][b * HH + t], enc_f(m));
    }
}

// ---------------- head ----------------
__global__ __launch_bounds__(64) void k_head(
    const float* __restrict__ r1w, const float* __restrict__ r1b,
    const float* __restrict__ r2w, const float* __restrict__ r2b,
    float* __restrict__ out)
{
    const int b = blockIdx.x;
    const int f = threadIdx.x;
    __shared__ float s[HH], tv[HH];

    s[f] = dec_f(g_cm[3][b * HH + f]);
    __syncthreads();

    float a = r1b[f];
#pragma unroll
    for (int h = 0; h < HH; h++) a += s[h] * r1w[f * 64 + h];
    tv[f] = tanhf(a);
    __syncthreads();

    if (f == 0) {
        float e = r2b[0];
        for (int h = 0; h < HH; h++) e += tv[h] * r2w[h];
        out[b] = e + (float)g_U0[b];
    }
}

// ---------------- launcher ----------------
extern "C" void kernel_launch(void* const* d_in, const int* in_sizes, int n_in,
                              void* d_out, int out_size)
{
    const float* pos = (const float*)d_in[0];
    const float* orR = (const float*)d_in[1];
    const int*   nbr = (const int*)  d_in[2];
    const float* w0  = (const float*)d_in[3];
    const float* b0  = (const float*)d_in[4];
    const float* w1  = (const float*)d_in[5];
    const float* b1  = (const float*)d_in[6];
    const float* g1  = (const float*)d_in[7];
    const float* be1 = (const float*)d_in[8];
    const float* w2  = (const float*)d_in[9];
    const float* b2  = (const float*)d_in[10];
    const float* g2  = (const float*)d_in[11];
    const float* be2 = (const float*)d_in[12];
    const float* w3  = (const float*)d_in[13];
    const float* b3  = (const float*)d_in[14];
    const float* p1w = (const float*)d_in[15];
    const float* p1b = (const float*)d_in[16];
    const float* p2w = (const float*)d_in[17];
    const float* p2b = (const float*)d_in[18];
    const float* p3w = (const float*)d_in[19];
    const float* p3b = (const float*)d_in[20];
    const float* r1w = (const float*)d_in[21];
    const float* r1b = (const float*)d_in[22];
    const float* r2w = (const float*)d_in[23];
    const float* r2b = (const float*)d_in[24];
    float* out = (float*)d_out;

    k_zero <<<1, 512>>>();
    k_edge1<<<EDGE_GRID, 128>>>(pos, orR, nbr, w0, b0, w1, b1);
    k_edge2<<<EDGE_GRID, 128>>>(g1, be1, w2, b2);
    k_edge3<<<EDGE_GRID, 128>>>(g2, be2, w3, b3);
    k_pe   <<<BB * 16, 128>>>(0, 0, 1, 1, p1w, p1b);
    k_pe   <<<BB * 16, 128>>>(1, 1, 2, 2, p2w, p2b);
    k_pe   <<<BB * 16, 128>>>(2, 2, 3, 0, p3w, p3b);
    k_head <<<BB, 64>>>(r1w, r1b, r2w, r2b, out);
}

// round 14
// speedup vs baseline: 1.8510x; 1.0001x over previous
#include <cuda_runtime.h>
#include <cuda_fp16.h>
#include <cuda_bf16.h>
#include <math.h>
#include <stdint.h>

#define BB   8
#define NP   2000
#define NNB  64
#define NF   19
#define HH   64
#define NNODE (BB*NP)          // 16000
#define NE   (BB*NP*NNB)       // 1024000
#define NCTA (NNODE/2)         // 8000 tiles (2 nodes / 128 edges each)
#define EDGE_GRID 592          // 148 SMs x 4 resident CTAs

// ---------------- device scratch ----------------
// fragment-native layout: [tile][tid 0..127][32 x half2]
__device__ __half g_tbuf[(size_t)NE * HH];
__device__ float  g_pooled[NNODE * HH];
__device__ float  g_zA[NNODE * HH];
__device__ float  g_zB[NNODE * HH];
__device__ unsigned g_cm[4][BB * HH];     // encoded col-max: 0=pooled,1=pe1,2=pe2,3=pe3
__device__ double g_sum1[HH], g_sq1[HH], g_sum2[HH], g_sq2[HH];
__device__ double g_U0[BB];

__device__ __forceinline__ const float* selz(int w) {
    return w == 0 ? g_pooled : (w == 1 ? g_zA : g_zB);
}

// monotonic float<->uint for atomicMax
__device__ __forceinline__ unsigned enc_f(float x) {
    unsigned u = __float_as_uint(x);
    return (u & 0x80000000u) ? ~u : (u | 0x80000000u);
}
__device__ __forceinline__ float dec_f(unsigned k) {
    return __uint_as_float((k & 0x80000000u) ? (k & 0x7FFFFFFFu) : ~k);
}

__device__ __forceinline__ uint32_t smem_u32(const void* p) {
    uint32_t a;
    asm("{ .reg .u64 t; cvta.to.shared.u64 t, %1; cvt.u32.u64 %0, t; }" : "=r"(a) : "l"(p));
    return a;
}

#define SW(o) ((o) ^ (((o) >> 3) & 0x70))

// ---- warp-level bf16 MMA ----
#define MMA16816(c, a, br0, br1) \
    asm volatile("mma.sync.aligned.m16n8k16.row.col.f32.bf16.bf16.f32 " \
                 "{%0,%1,%2,%3}, {%4,%5,%6,%7}, {%8,%9}, {%0,%1,%2,%3};" \
                 : "+f"((c)[0]), "+f"((c)[1]), "+f"((c)[2]), "+f"((c)[3]) \
                 : "r"((a)[0]), "r"((a)[1]), "r"((a)[2]), "r"((a)[3]), \
                   "r"(br0), "r"(br1))

__device__ __forceinline__ void ldmA(uint32_t a[4], const unsigned char* As,
                                     int m0, int k0, int lane) {
    int row = m0 + (lane & 7) + ((lane & 8) ? 8 : 0);
    int kc  = k0 + ((lane & 16) ? 8 : 0);
    uint32_t addr = smem_u32(As + SW(row * 128 + kc * 2));
    asm volatile("ldmatrix.sync.aligned.m8n8.x4.shared.b16 {%0,%1,%2,%3}, [%4];"
                 : "=r"(a[0]), "=r"(a[1]), "=r"(a[2]), "=r"(a[3]) : "r"(addr));
}

__device__ __forceinline__ void ldmB(uint32_t b[4], const unsigned char* Bs,
                                     int n0, int k0, int lane) {
    int row = n0 + (lane & 7) + ((lane & 16) ? 8 : 0);
    int kc  = k0 + ((lane & 8) ? 8 : 0);
    uint32_t addr = smem_u32(Bs + SW(row * 128 + kc * 2));
    asm volatile("ldmatrix.sync.aligned.m8n8.x4.shared.b16 {%0,%1,%2,%3}, [%4];"
                 : "=r"(b[0]), "=r"(b[1]), "=r"(b[2]), "=r"(b[3]) : "r"(addr));
}

template <int KS>
__device__ __forceinline__ void mma_layer(const unsigned char* As, const unsigned char* Bs,
                                          int wid, int lane, float c[2][8][4]) {
#pragma unroll
    for (int i = 0; i < 2; i++)
#pragma unroll
        for (int j = 0; j < 8; j++)
#pragma unroll
            for (int q = 0; q < 4; q++) c[i][j][q] = 0.f;
#pragma unroll
    for (int ks = 0; ks < KS; ks++) {
        int k0 = ks * 16;
        uint32_t a0[4], a1[4];
        ldmA(a0, As, wid * 32, k0, lane);
        ldmA(a1, As, wid * 32 + 16, k0, lane);
#pragma unroll
        for (int jt = 0; jt < 4; jt++) {
            uint32_t b[4];
            ldmB(b, Bs, jt * 16, k0, lane);
            MMA16816(c[0][jt * 2],     a0, b[0], b[1]);
            MMA16816(c[0][jt * 2 + 1], a0, b[2], b[3]);
            MMA16816(c[1][jt * 2],     a1, b[0], b[1]);
            MMA16816(c[1][jt * 2 + 1], a1, b[2], b[3]);
        }
    }
}

// stage weights [64][64] row-major into swizzled 8KB B tile
__device__ __forceinline__ void stage_w(const float* __restrict__ w,
                                        unsigned char* Bs, int t) {
    for (int idx = t; idx < 2048; idx += 128) {
        int j = idx >> 5, k2 = idx & 31;
        *(__nv_bfloat162*)(Bs + SW(j * 128 + k2 * 4)) =
            __floats2bfloat162_rn(w[j * 64 + 2 * k2], w[j * 64 + 2 * k2 + 1]);
    }
}

// ---------------- zero/init accumulators ----------------
__global__ void k_zero() {
    int t = threadIdx.x;
    if (t < HH) { g_sum1[t] = 0.0; g_sq1[t] = 0.0; g_sum2[t] = 0.0; g_sq2[t] = 0.0; }
    if (t < BB) g_U0[t] = 0.0;
    for (int i = t; i < 4 * BB * HH; i += 512) g_cm[i >> 9][i & 511] = 0u;
}

// epilogue (smem-accumulating variant, used by edge2)
__device__ __forceinline__ void epi_store_stats(
    float c[2][8][4], const float* bias, __half* tbase,
    float2* ps, float2* pq, int wid, int lane)
{
    const int rcls = wid * 8 + (lane >> 2);
    const int L = lane & 3;
    __half2 o[32];
#pragma unroll
    for (int j = 0; j < 8; j++) {
        const int c0 = j * 8 + L * 2;
        float b0v = bias[c0], b1v = bias[c0 + 1];
        __half2 h0 = __floats2half2_rn(c[0][j][0] + b0v, c[0][j][1] + b1v);
        __half2 h1 = __floats2half2_rn(c[0][j][2] + b0v, c[0][j][3] + b1v);
        __half2 h2 = __floats2half2_rn(c[1][j][0] + b0v, c[1][j][1] + b1v);
        __half2 h3 = __floats2half2_rn(c[1][j][2] + b0v, c[1][j][3] + b1v);
        o[j * 2]          = h0;
        o[j * 2 + 1]      = h1;
        o[16 + j * 2]     = h2;
        o[16 + j * 2 + 1] = h3;
        float2 v0 = __half22float2(h0), v1 = __half22float2(h1);
        float2 v2 = __half22float2(h2), v3 = __half22float2(h3);
        float sx = (v0.x + v1.x) + (v2.x + v3.x);
        float sy = (v0.y + v1.y) + (v2.y + v3.y);
        float qx = (v0.x * v0.x + v1.x * v1.x) + (v2.x * v2.x + v3.x * v3.x);
        float qy = (v0.y * v0.y + v1.y * v1.y) + (v2.y * v2.y + v3.y * v3.y);
        int slot = rcls * 33 + j * 4 + L;
        float2 a = ps[slot]; a.x += sx; a.y += sy; ps[slot] = a;
        float2 qv = pq[slot]; qv.x += qx; qv.y += qy; pq[slot] = qv;
    }
#pragma unroll
    for (int q = 0; q < 8; q++) *(uint4*)(tbase + 8 * q) = ((uint4*)o)[q];
}

// consumer: fragment-native row -> BN+relu -> As (own warp rows only)
__device__ __forceinline__ void consume_to_As(
    const uint4 rv[8], unsigned char* As, const float* sc, const float* sh,
    int wid, int lane)
{
    const int rbase = wid * 32 + (lane >> 2);
    const int c0b = (lane & 3) * 2;
#pragma unroll
    for (int s2 = 0; s2 < 8; s2++) {
        const __half2* hp = (const __half2*)&rv[s2];
#pragma unroll
        for (int u = 0; u < 4; u++) {
            int s = s2 * 4 + u;
            int i = s >> 4, j = (s >> 1) & 7, p = s & 1;
            int row = rbase + i * 16 + p * 8;
            int c0 = j * 8 + c0b;
            float2 v = __half22float2(hp[u]);
            float h0 = fmaxf(v.x * sc[c0]     + sh[c0],     0.f);
            float h1 = fmaxf(v.y * sc[c0 + 1] + sh[c0 + 1], 0.f);
            *(__nv_bfloat162*)(As + SW(row * 128 + c0 * 2)) = __floats2bfloat162_rn(h0, h1);
        }
    }
}

// ---------------- stage 1 (persistent, register stats accumulators) ----------------
__global__ __launch_bounds__(128, 4)
void k_edge1(const float* __restrict__ pos, const float* __restrict__ orR,
             const int* __restrict__ nbr,
             const float* __restrict__ w0, const float* __restrict__ b0,
             const float* __restrict__ w1, const float* __restrict__ b1)
{
    __shared__ __align__(128) unsigned char As[16384];
    __shared__ __align__(128) unsigned char Bs0[8192], Bs1[8192];
    __shared__ float b0s[64], b1s[64], prb[4][8];

    const int t = threadIdx.x, wid = t >> 5, lane = t & 31;
    const int L = lane & 3;
    const int rcls = wid * 8 + (lane >> 2);

    if (t < 64) { b0s[t] = b0[t]; b1s[t] = b1[t]; }
    if (lane < 8) prb[wid][lane] = 0.f;

    float2 accS[8], accQ[8];
#pragma unroll
    for (int j = 0; j < 8; j++) {
        accS[j] = make_float2(0.f, 0.f);
        accQ[j] = make_float2(0.f, 0.f);
    }

    // stage w0 (zero-padded to K=32) and w1, once per CTA
    for (int idx = t; idx < 1024; idx += 128) {
        int j = idx >> 4, k2 = idx & 15;
        int c0 = 2 * k2, c1 = c0 + 1;
        float v0 = (c0 < NF) ? w0[j * NF + c0] : 0.f;
        float v1 = (c1 < NF) ? w0[j * NF + c1] : 0.f;
        *(__nv_bfloat162*)(Bs0 + SW(j * 128 + k2 * 4)) = __floats2bfloat162_rn(v0, v1);
    }
    stage_w(w1, Bs1, t);
    __syncthreads();

    for (int tile = blockIdx.x; tile < NCTA; tile += EDGE_GRID) {
        const int node0 = tile * 2;
        const int b = node0 / NP;
        const int node = node0 + (t >> 6);
        const int m    = t & 63;
        const int jn   = nbr[node * NNB + m];
        const int nidx = b * NP + jn;

        float d0 = pos[nidx * 3 + 0] - pos[node * 3 + 0]; d0 -= rintf(d0);
        float d1 = pos[nidx * 3 + 1] - pos[node * 3 + 1]; d1 -= rintf(d1);
        float d2 = pos[nidx * 3 + 2] - pos[node * 3 + 2]; d2 -= rintf(d2);
        float r2 = d0 * d0 + d1 * d1 + d2 * d2 + 1e-12f;
        float R  = sqrtf(r2);
        float inv = 1.0f / R;

        float Ris[9], Rj[9];
#pragma unroll
        for (int k = 0; k < 9; k++) Ris[k] = orR[node * 9 + k];
#pragma unroll
        for (int k = 0; k < 9; k++) Rj[k]  = orR[nidx * 9 + k];

        float f[NF];
        f[0] = d0 * inv; f[1] = d1 * inv; f[2] = d2 * inv; f[3] = R;
#pragma unroll
        for (int j = 0; j < 3; j++) {
            f[4 + j] = f[0] * Ris[j] + f[1] * Ris[3 + j] + f[2] * Ris[6 + j];
            f[7 + j] = f[0] * Rj[j]  + f[1] * Rj[3 + j]  + f[2] * Rj[6 + j];
        }
#pragma unroll
        for (int j = 0; j < 3; j++)
#pragma unroll
            for (int k = 0; k < 3; k++)
                f[10 + j * 3 + k] = Ris[j] * Rj[k] + Ris[3 + j] * Rj[3 + k] + Ris[6 + j] * Rj[6 + k];

        {   // prior: warp reduce, accumulate per-warp per-batch (exclusive slots)
            float tp = 0.01f * inv;
            float tp2 = tp * tp, tp4 = tp2 * tp2, tp8 = tp4 * tp4;
            float pr = tp8 * tp4;
#pragma unroll
            for (int off = 16; off > 0; off >>= 1)
                pr += __shfl_xor_sync(0xffffffffu, pr, off);
            if (lane == 0) prb[wid][b] += pr;
        }

#pragma unroll
        for (int j2 = 0; j2 < 16; j2++) {
            float v0 = 0.f, v1 = 0.f;
            if (j2 < 9) { v0 = f[2 * j2]; v1 = f[2 * j2 + 1]; }
            else if (j2 == 9) { v0 = f[18]; }
            *(__nv_bfloat162*)(As + SW(t * 128 + j2 * 4)) = __floats2bfloat162_rn(v0, v1);
        }
        __syncwarp();

        float c[2][8][4];
        mma_layer<2>(As, Bs0, wid, lane, c);

        // epilogue 0: relu(+b0) -> As (own warp rows)
        {
            const int r0 = wid * 32 + (lane >> 2);
#pragma unroll
            for (int j = 0; j < 8; j++) {
                const int c0 = j * 8 + L * 2;
                float b0v = b0s[c0], b1v = b0s[c0 + 1];
                *(__nv_bfloat162*)(As + SW(r0 * 128 + c0 * 2)) =
                    __floats2bfloat162_rn(fmaxf(c[0][j][0] + b0v, 0.f), fmaxf(c[0][j][1] + b1v, 0.f));
                *(__nv_bfloat162*)(As + SW((r0 + 8) * 128 + c0 * 2)) =
                    __floats2bfloat162_rn(fmaxf(c[0][j][2] + b0v, 0.f), fmaxf(c[0][j][3] + b1v, 0.f));
                *(__nv_bfloat162*)(As + SW((r0 + 16) * 128 + c0 * 2)) =
                    __floats2bfloat162_rn(fmaxf(c[1][j][0] + b0v, 0.f), fmaxf(c[1][j][1] + b1v, 0.f));
                *(__nv_bfloat162*)(As + SW((r0 + 24) * 128 + c0 * 2)) =
                    __floats2bfloat162_rn(fmaxf(c[1][j][2] + b0v, 0.f), fmaxf(c[1][j][3] + b1v, 0.f));
            }
        }
        __syncwarp();

        mma_layer<4>(As, Bs1, wid, lane, c);

        // epilogue 1: +b1, round fp16, store coalesced, accumulate stats in regs
        {
            __half2 o[32];
#pragma unroll
            for (int j = 0; j < 8; j++) {
                const int c0 = j * 8 + L * 2;
                float b0v = b1s[c0], b1v = b1s[c0 + 1];
                __half2 h0 = __floats2half2_rn(c[0][j][0] + b0v, c[0][j][1] + b1v);
                __half2 h1 = __floats2half2_rn(c[0][j][2] + b0v, c[0][j][3] + b1v);
                __half2 h2 = __floats2half2_rn(c[1][j][0] + b0v, c[1][j][1] + b1v);
                __half2 h3 = __floats2half2_rn(c[1][j][2] + b0v, c[1][j][3] + b1v);
                o[j * 2]          = h0;
                o[j * 2 + 1]      = h1;
                o[16 + j * 2]     = h2;
                o[16 + j * 2 + 1] = h3;
                float2 v0 = __half22float2(h0), v1 = __half22float2(h1);
                float2 v2 = __half22float2(h2), v3 = __half22float2(h3);
                accS[j].x += (v0.x + v1.x) + (v2.x + v3.x);
                accS[j].y += (v0.y + v1.y) + (v2.y + v3.y);
                accQ[j].x += (v0.x * v0.x + v1.x * v1.x) + (v2.x * v2.x + v3.x * v3.x);
                accQ[j].y += (v0.y * v0.y + v1.y * v1.y) + (v2.y * v2.y + v3.y * v3.y);
            }
            __half* tbase = g_tbuf + ((size_t)tile * 128 + t) * 64;
#pragma unroll
            for (int q = 0; q < 8; q++) *(uint4*)(tbase + 8 * q) = ((uint4*)o)[q];
        }
    }

    // final stats reduction: overlay As (now dead) as two stride-32 float2 arrays
    __syncthreads();
    {
        float2* ps2 = (float2*)As;               // 8192 B
        float2* pq2 = (float2*)(As + 8192);      // 8192 B
#pragma unroll
        for (int j = 0; j < 8; j++) {
            ps2[rcls * 32 + j * 4 + L] = accS[j];
            pq2[rcls * 32 + j * 4 + L] = accQ[j];
        }
    }
    __syncthreads();
    if (t < 32) {
        const float2* ps2 = (const float2*)As;
        const float2* pq2 = (const float2*)(As + 8192);
        float2 s = make_float2(0.f, 0.f), q = make_float2(0.f, 0.f);
#pragma unroll 8
        for (int r = 0; r < 32; r++) {
            float2 a = ps2[r * 32 + t], qq = pq2[r * 32 + t];
            s.x += a.x; s.y += a.y; q.x += qq.x; q.y += qq.y;
        }
        int c0 = (t >> 2) * 8 + (t & 3) * 2;
        atomicAdd(&g_sum1[c0],     (double)s.x);
        atomicAdd(&g_sum1[c0 + 1], (double)s.y);
        atomicAdd(&g_sq1[c0],      (double)q.x);
        atomicAdd(&g_sq1[c0 + 1],  (double)q.y);
    }
    if (t < 8) {
        float p = (prb[0][t] + prb[1][t]) + (prb[2][t] + prb[3][t]);
        if (p != 0.f) atomicAdd(&g_U0[t], (double)p);
    }
}

// ---------------- stage 2 (persistent) ----------------
__global__ __launch_bounds__(128, 4)
void k_edge2(const float* __restrict__ g1, const float* __restrict__ be1,
             const float* __restrict__ w2, const float* __restrict__ b2)
{
    __shared__ __align__(128) unsigned char As[16384];
    __shared__ __align__(128) unsigned char Bs[8192];
    __shared__ float2 ps[32 * 33], pq[32 * 33];
    __shared__ float b2s[64], sc[64], sh[64];

    const int t = threadIdx.x, wid = t >> 5, lane = t & 31;

    if (t < 64) {
        b2s[t] = b2[t];
        double mean = g_sum1[t] / (double)NE;
        double var  = g_sq1[t] / (double)NE - mean * mean;
        float istd  = rsqrtf((float)var + 1e-5f);
        float scale = g1[t] * istd;
        sc[t] = scale;
        sh[t] = be1[t] - (float)mean * scale;
    }
    {
        const int rcls = wid * 8 + (lane >> 2), L = lane & 3;
#pragma unroll
        for (int j = 0; j < 8; j++) {
            ps[rcls * 33 + j * 4 + L] = make_float2(0.f, 0.f);
            pq[rcls * 33 + j * 4 + L] = make_float2(0.f, 0.f);
        }
    }
    stage_w(w2, Bs, t);
    __syncthreads();

    for (int tile = blockIdx.x; tile < NCTA; tile += EDGE_GRID) {
        uint4 rv[8];
        const uint4* rp = (const uint4*)(g_tbuf + ((size_t)tile * 128 + t) * 64);
#pragma unroll
        for (int q = 0; q < 8; q++) rv[q] = rp[q];

        consume_to_As(rv, As, sc, sh, wid, lane);
        __syncwarp();

        float c[2][8][4];
        mma_layer<4>(As, Bs, wid, lane, c);
        epi_store_stats(c, b2s, g_tbuf + ((size_t)tile * 128 + t) * 64, ps, pq, wid, lane);
    }

    __syncthreads();
    if (t < 32) {
        float2 s = make_float2(0.f, 0.f), q = make_float2(0.f, 0.f);
#pragma unroll 8
        for (int r = 0; r < 32; r++) {
            float2 a = ps[r * 33 + t], qq = pq[r * 33 + t];
            s.x += a.x; s.y += a.y; q.x += qq.x; q.y += qq.y;
        }
        int c0 = (t >> 2) * 8 + (t & 3) * 2;
        atomicAdd(&g_sum2[c0],     (double)s.x);
        atomicAdd(&g_sum2[c0 + 1], (double)s.y);
        atomicAdd(&g_sq2[c0],      (double)q.x);
        atomicAdd(&g_sq2[c0 + 1],  (double)q.y);
    }
}

// ---------------- stage 3 (persistent) + fused colmax of pooled ----------------
__global__ __launch_bounds__(128, 4)
void k_edge3(const float* __restrict__ g2, const float* __restrict__ be2,
             const float* __restrict__ w3, const float* __restrict__ b3)
{
    __shared__ __align__(128) unsigned char As[16384];
    __shared__ __align__(128) unsigned char Bs[8192];
    __shared__ float2 ps[32 * 33];
    __shared__ float pm[128];
    __shared__ float b3s[64], sc[64], sh[64];

    const int t = threadIdx.x, wid = t >> 5, lane = t & 31;

    if (t < 64) {
        b3s[t] = b3[t];
        double mean = g_sum2[t] / (double)NE;
        double var  = g_sq2[t] / (double)NE - mean * mean;
        float istd  = rsqrtf((float)var + 1e-5f);
        float scale = g2[t] * istd;
        sc[t] = scale;
        sh[t] = be2[t] - (float)mean * scale;
    }
    stage_w(w3, Bs, t);
    __syncthreads();

    for (int tile = blockIdx.x; tile < NCTA; tile += EDGE_GRID) {
        const int node0 = tile * 2;
        const int b = node0 / NP;

        uint4 rv[8];
        const uint4* rp = (const uint4*)(g_tbuf + ((size_t)tile * 128 + t) * 64);
#pragma unroll
        for (int q = 0; q < 8; q++) rv[q] = rp[q];

        consume_to_As(rv, As, sc, sh, wid, lane);
        __syncwarp();

        float c[2][8][4];
        mma_layer<4>(As, Bs, wid, lane, c);

        {
            const int rcls = wid * 8 + (lane >> 2);
            const int L = lane & 3;
#pragma unroll
            for (int j = 0; j < 8; j++) {
                float sx = (c[0][j][0] + c[0][j][2]) + (c[1][j][0] + c[1][j][2]);
                float sy = (c[0][j][1] + c[0][j][3]) + (c[1][j][1] + c[1][j][3]);
                ps[rcls * 33 + j * 4 + L] = make_float2(sx, sy);
            }
        }
        __syncthreads();

        {
            int nodesel = t >> 6;
            int cidx = t & 63;
            int p = (cidx >> 3) * 4 + ((cidx & 7) >> 1);
            int comp = cidx & 1;
            float s = 0.f;
            int rbase = nodesel * 16;
#pragma unroll 8
            for (int r = 0; r < 16; r++) {
                float2 a = ps[(rbase + r) * 33 + p];
                s += comp ? a.y : a.x;
            }
            s = s * (1.0f / NNB) + b3s[cidx];
            g_pooled[(node0 + nodesel) * HH + cidx] = s;
            pm[t] = s;
        }
        __syncthreads();
        if (t < 64)
            atomicMax(&g_cm[0][b * HH + t], enc_f(fmaxf(pm[t], pm[t + 64])));
    }
}

// ---------------- PermEqui1_max + fused output colmax ----------------
__global__ __launch_bounds__(128) void k_pe(int insel, int cmin, int cmout, int outsel,
    const float* __restrict__ w, const float* __restrict__ bias)
{
    __shared__ float ws[HH * HH], cf[HH], cms[HH];
    __shared__ float wm[HH * 4];
    const int bx = blockIdx.x;
    const int b  = bx >> 4;
    const int rb = bx & 15;
    const int t  = threadIdx.x;
    const int wid = t >> 5, lane = t & 31;
    const float* zin = selz(insel);
    float* zout = (outsel == 1) ? g_zA : ((outsel == 2) ? g_zB : 0);

    for (int i = t; i < HH * HH; i += 128) ws[i] = w[i];
    if (t < HH) cms[t] = dec_f(g_cm[cmin][b * HH + t]);
    __syncthreads();

    if (t < HH) {
        float a0 = bias[t], a1 = 0.f, a2 = 0.f, a3 = 0.f;
#pragma unroll
        for (int h = 0; h < HH; h += 4) {
            a0 -= cms[h]     * ws[t * 64 + h];
            a1 -= cms[h + 1] * ws[t * 64 + h + 1];
            a2 -= cms[h + 2] * ws[t * 64 + h + 2];
            a3 -= cms[h + 3] * ws[t * 64 + h + 3];
        }
        cf[t] = (a0 + a1) + (a2 + a3);
    }
    __syncthreads();

    const int n = rb * 125 + t;
    const bool valid = (t < 125);
    float z[HH];
    const float* zr = &zin[((size_t)b * NP + (valid ? n : 0)) * HH];
#pragma unroll
    for (int h = 0; h < HH; h++) z[h] = zr[h];
    float* orow = zout ? &zout[((size_t)b * NP + n) * HH] : 0;

#pragma unroll 4
    for (int fj = 0; fj < HH; fj++) {
        float a0 = cf[fj], a1 = 0.f, a2 = 0.f, a3 = 0.f;
#pragma unroll
        for (int h = 0; h < HH; h += 4) {
            a0 += z[h]     * ws[fj * 64 + h];
            a1 += z[h + 1] * ws[fj * 64 + h + 1];
            a2 += z[h + 2] * ws[fj * 64 + h + 2];
            a3 += z[h + 3] * ws[fj * 64 + h + 3];
        }
        float v = tanhf((a0 + a1) + (a2 + a3));
        if (valid && orow) orow[fj] = v;
        float mv = valid ? v : -INFINITY;
#pragma unroll
        for (int off = 16; off > 0; off >>= 1)
            mv = fmaxf(mv, __shfl_xor_sync(0xffffffffu, mv, off));
        if (lane == 0) wm[fj * 4 + wid] = mv;
    }
    __syncthreads();
    if (t < HH) {
        float m = fmaxf(fmaxf(wm[t * 4], wm[t * 4 + 1]), fmaxf(wm[t * 4 + 2], wm[t * 4 + 3]));
        atomicMax(&g_cm[cmout][b * HH + t], enc_f(m));
    }
}

// ---------------- head ----------------
__global__ __launch_bounds__(64) void k_head(
    const float* __restrict__ r1w, const float* __restrict__ r1b,
    const float* __restrict__ r2w, const float* __restrict__ r2b,
    float* __restrict__ out)
{
    const int b = blockIdx.x;
    const int f = threadIdx.x;
    __shared__ float s[HH], tv[HH];

    s[f] = dec_f(g_cm[3][b * HH + f]);
    __syncthreads();

    float a = r1b[f];
#pragma unroll
    for (int h = 0; h < HH; h++) a += s[h] * r1w[f * 64 + h];
    tv[f] = tanhf(a);
    __syncthreads();

    if (f == 0) {
        float e = r2b[0];
        for (int h = 0; h < HH; h++) e += tv[h] * r2w[h];
        out[b] = e + (float)g_U0[b];
    }
}

// ---------------- launcher ----------------
extern "C" void kernel_launch(void* const* d_in, const int* in_sizes, int n_in,
                              void* d_out, int out_size)
{
    const float* pos = (const float*)d_in[0];
    const float* orR = (const float*)d_in[1];
    const int*   nbr = (const int*)  d_in[2];
    const float* w0  = (const float*)d_in[3];
    const float* b0  = (const float*)d_in[4];
    const float* w1  = (const float*)d_in[5];
    const float* b1  = (const float*)d_in[6];
    const float* g1  = (const float*)d_in[7];
    const float* be1 = (const float*)d_in[8];
    const float* w2  = (const float*)d_in[9];
    const float* b2  = (const float*)d_in[10];
    const float* g2  = (const float*)d_in[11];
    const float* be2 = (const float*)d_in[12];
    const float* w3  = (const float*)d_in[13];
    const float* b3  = (const float*)d_in[14];
    const float* p1w = (const float*)d_in[15];
    const float* p1b = (const float*)d_in[16];
    const float* p2w = (const float*)d_in[17];
    const float* p2b = (const float*)d_in[18];
    const float* p3w = (const float*)d_in[19];
    const float* p3b = (const float*)d_in[20];
    const float* r1w = (const float*)d_in[21];
    const float* r1b = (const float*)d_in[22];
    const float* r2w = (const float*)d_in[23];
    const float* r2b = (const float*)d_in[24];
    float* out = (float*)d_out;

    k_zero <<<1, 512>>>();
    k_edge1<<<EDGE_GRID, 128>>>(pos, orR, nbr, w0, b0, w1, b1);
    k_edge2<<<EDGE_GRID, 128>>>(g1, be1, w2, b2);
    k_edge3<<<EDGE_GRID, 128>>>(g2, be2, w3, b3);
    k_pe   <<<BB * 16, 128>>>(0, 0, 1, 1, p1w, p1b);
    k_pe   <<<BB * 16, 128>>>(1, 1, 2, 2, p2w, p2b);
    k_pe   <<<BB * 16, 128>>>(2, 2, 3, 0, p3w, p3b);
    k_head <<<BB, 64>>>(r1w, r1b, r2w, r2b, out);
}

// round 15
// speedup vs baseline: 1.9683x; 1.0634x over previous
#include <cuda_runtime.h>
#include <cuda_fp16.h>
#include <cuda_bf16.h>
#include <math.h>
#include <stdint.h>

#define BB   8
#define NP   2000
#define NNB  64
#define NF   19
#define HH   64
#define NNODE (BB*NP)          // 16000
#define NE   (BB*NP*NNB)       // 1024000
#define NCTA (NNODE/2)         // 8000 tiles (2 nodes / 128 edges each)
#define EDGE_GRID 592          // 148 SMs x 4 resident CTAs

// ---------------- device scratch ----------------
// fragment-native layout: [tile][tid 0..127][32 x half2]
__device__ __half g_tbuf[(size_t)NE * HH];
__device__ float  g_pooled[NNODE * HH];
__device__ float  g_zA[NNODE * HH];
__device__ float  g_zB[NNODE * HH];
__device__ unsigned g_cm[4][BB * HH];     // encoded col-max: 0=pooled,1=pe1,2=pe2,3=pe3
__device__ double g_sum1[HH], g_sq1[HH], g_sum2[HH], g_sq2[HH];
__device__ double g_U0[BB];

__device__ __forceinline__ const float* selz(int w) {
    return w == 0 ? g_pooled : (w == 1 ? g_zA : g_zB);
}

// monotonic float<->uint for atomicMax
__device__ __forceinline__ unsigned enc_f(float x) {
    unsigned u = __float_as_uint(x);
    return (u & 0x80000000u) ? ~u : (u | 0x80000000u);
}
__device__ __forceinline__ float dec_f(unsigned k) {
    return __uint_as_float((k & 0x80000000u) ? (k & 0x7FFFFFFFu) : ~k);
}

__device__ __forceinline__ uint32_t smem_u32(const void* p) {
    uint32_t a;
    asm("{ .reg .u64 t; cvta.to.shared.u64 t, %1; cvt.u32.u64 %0, t; }" : "=r"(a) : "l"(p));
    return a;
}

#define SW(o) ((o) ^ (((o) >> 3) & 0x70))

// ---- warp-level bf16 MMA ----
#define MMA16816(c, a, br0, br1) \
    asm volatile("mma.sync.aligned.m16n8k16.row.col.f32.bf16.bf16.f32 " \
                 "{%0,%1,%2,%3}, {%4,%5,%6,%7}, {%8,%9}, {%0,%1,%2,%3};" \
                 : "+f"((c)[0]), "+f"((c)[1]), "+f"((c)[2]), "+f"((c)[3]) \
                 : "r"((a)[0]), "r"((a)[1]), "r"((a)[2]), "r"((a)[3]), \
                   "r"(br0), "r"(br1))

__device__ __forceinline__ void ldmA(uint32_t a[4], const unsigned char* As,
                                     int m0, int k0, int lane) {
    int row = m0 + (lane & 7) + ((lane & 8) ? 8 : 0);
    int kc  = k0 + ((lane & 16) ? 8 : 0);
    uint32_t addr = smem_u32(As + SW(row * 128 + kc * 2));
    asm volatile("ldmatrix.sync.aligned.m8n8.x4.shared.b16 {%0,%1,%2,%3}, [%4];"
                 : "=r"(a[0]), "=r"(a[1]), "=r"(a[2]), "=r"(a[3]) : "r"(addr));
}

__device__ __forceinline__ void ldmB(uint32_t b[4], const unsigned char* Bs,
                                     int n0, int k0, int lane) {
    int row = n0 + (lane & 7) + ((lane & 16) ? 8 : 0);
    int kc  = k0 + ((lane & 8) ? 8 : 0);
    uint32_t addr = smem_u32(Bs + SW(row * 128 + kc * 2));
    asm volatile("ldmatrix.sync.aligned.m8n8.x4.shared.b16 {%0,%1,%2,%3}, [%4];"
                 : "=r"(b[0]), "=r"(b[1]), "=r"(b[2]), "=r"(b[3]) : "r"(addr));
}

__device__ __forceinline__ void zero_c(float c[2][8][4]) {
#pragma unroll
    for (int i = 0; i < 2; i++)
#pragma unroll
        for (int j = 0; j < 8; j++)
#pragma unroll
            for (int q = 0; q < 4; q++) c[i][j][q] = 0.f;
}

// smem-A mma layer (used only for edge1 layer0)
template <int KS>
__device__ __forceinline__ void mma_layer(const unsigned char* As, const unsigned char* Bs,
                                          int wid, int lane, float c[2][8][4]) {
    zero_c(c);
#pragma unroll
    for (int ks = 0; ks < KS; ks++) {
        int k0 = ks * 16;
        uint32_t a0[4], a1[4];
        ldmA(a0, As, wid * 32, k0, lane);
        ldmA(a1, As, wid * 32 + 16, k0, lane);
#pragma unroll
        for (int jt = 0; jt < 4; jt++) {
            uint32_t b[4];
            ldmB(b, Bs, jt * 16, k0, lane);
            MMA16816(c[0][jt * 2],     a0, b[0], b[1]);
            MMA16816(c[0][jt * 2 + 1], a0, b[2], b[3]);
            MMA16816(c[1][jt * 2],     a1, b[0], b[1]);
            MMA16816(c[1][jt * 2 + 1], a1, b[2], b[3]);
        }
    }
}

// register-A mma layer (K=64): a-fragments supplied per k-chunk
__device__ __forceinline__ void mma_layer_regA(const uint32_t ha0[4][4], const uint32_t ha1[4][4],
                                               const unsigned char* Bs, int lane, float c[2][8][4]) {
    zero_c(c);
#pragma unroll
    for (int ks = 0; ks < 4; ks++) {
#pragma unroll
        for (int jt = 0; jt < 4; jt++) {
            uint32_t b[4];
            ldmB(b, Bs, jt * 16, ks * 16, lane);
            MMA16816(c[0][jt * 2],     ha0[ks], b[0], b[1]);
            MMA16816(c[0][jt * 2 + 1], ha0[ks], b[2], b[3]);
            MMA16816(c[1][jt * 2],     ha1[ks], b[0], b[1]);
            MMA16816(c[1][jt * 2 + 1], ha1[ks], b[2], b[3]);
        }
    }
}

__device__ __forceinline__ uint32_t pkrelu(float x, float y) {
    __nv_bfloat162 b = __floats2bfloat162_rn(fmaxf(x, 0.f), fmaxf(y, 0.f));
    return *(uint32_t*)&b;
}

// BN+relu a scratch uint4 (4 half2 = C-fragment slots of one (i,ks)) into an A-fragment
__device__ __forceinline__ void bn_pack(const uint4 rvq, const float* sc, const float* sh,
                                        int cA, uint32_t a[4]) {
    const __half2* hp = (const __half2*)&rvq;
    float sA0 = sc[cA],     sA1 = sc[cA + 1], hA0 = sh[cA],     hA1 = sh[cA + 1];
    float sB0 = sc[cA + 8], sB1 = sc[cA + 9], hB0 = sh[cA + 8], hB1 = sh[cA + 9];
    float2 v0 = __half22float2(hp[0]);
    float2 v1 = __half22float2(hp[1]);
    float2 v2 = __half22float2(hp[2]);
    float2 v3 = __half22float2(hp[3]);
    a[0] = pkrelu(v0.x * sA0 + hA0, v0.y * sA1 + hA1);
    a[1] = pkrelu(v1.x * sA0 + hA0, v1.y * sA1 + hA1);
    a[2] = pkrelu(v2.x * sB0 + hB0, v2.y * sB1 + hB1);
    a[3] = pkrelu(v3.x * sB0 + hB0, v3.y * sB1 + hB1);
}

// stage weights [64][64] row-major into swizzled 8KB B tile
__device__ __forceinline__ void stage_w(const float* __restrict__ w,
                                        unsigned char* Bs, int t) {
    for (int idx = t; idx < 2048; idx += 128) {
        int j = idx >> 5, k2 = idx & 31;
        *(__nv_bfloat162*)(Bs + SW(j * 128 + k2 * 4)) =
            __floats2bfloat162_rn(w[j * 64 + 2 * k2], w[j * 64 + 2 * k2 + 1]);
    }
}

// ---------------- zero/init accumulators ----------------
__global__ void k_zero() {
    int t = threadIdx.x;
    if (t < HH) { g_sum1[t] = 0.0; g_sq1[t] = 0.0; g_sum2[t] = 0.0; g_sq2[t] = 0.0; }
    if (t < BB) g_U0[t] = 0.0;
    for (int i = t; i < 4 * BB * HH; i += 512) g_cm[i >> 9][i & 511] = 0u;
}

// epilogue (smem-accumulating stats, used by edge2)
__device__ __forceinline__ void epi_store_stats(
    float c[2][8][4], const float* bias, __half* tbase,
    float2* ps, float2* pq, int wid, int lane)
{
    const int rcls = wid * 8 + (lane >> 2);
    const int L = lane & 3;
    __half2 o[32];
#pragma unroll
    for (int j = 0; j < 8; j++) {
        const int c0 = j * 8 + L * 2;
        float b0v = bias[c0], b1v = bias[c0 + 1];
        __half2 h0 = __floats2half2_rn(c[0][j][0] + b0v, c[0][j][1] + b1v);
        __half2 h1 = __floats2half2_rn(c[0][j][2] + b0v, c[0][j][3] + b1v);
        __half2 h2 = __floats2half2_rn(c[1][j][0] + b0v, c[1][j][1] + b1v);
        __half2 h3 = __floats2half2_rn(c[1][j][2] + b0v, c[1][j][3] + b1v);
        o[j * 2]          = h0;
        o[j * 2 + 1]      = h1;
        o[16 + j * 2]     = h2;
        o[16 + j * 2 + 1] = h3;
        float2 v0 = __half22float2(h0), v1 = __half22float2(h1);
        float2 v2 = __half22float2(h2), v3 = __half22float2(h3);
        float sx = (v0.x + v1.x) + (v2.x + v3.x);
        float sy = (v0.y + v1.y) + (v2.y + v3.y);
        float qx = (v0.x * v0.x + v1.x * v1.x) + (v2.x * v2.x + v3.x * v3.x);
        float qy = (v0.y * v0.y + v1.y * v1.y) + (v2.y * v2.y + v3.y * v3.y);
        int slot = rcls * 33 + j * 4 + L;
        float2 a = ps[slot]; a.x += sx; a.y += sy; ps[slot] = a;
        float2 qv = pq[slot]; qv.x += qx; qv.y += qy; pq[slot] = qv;
    }
#pragma unroll
    for (int q = 0; q < 8; q++) *(uint4*)(tbase + 8 * q) = ((uint4*)o)[q];
}

// ---------------- stage 1 (persistent, register A-fragments for layer1) ----------------
__global__ __launch_bounds__(128, 4)
void k_edge1(const float* __restrict__ pos, const float* __restrict__ orR,
             const int* __restrict__ nbr,
             const float* __restrict__ w0, const float* __restrict__ b0,
             const float* __restrict__ w1, const float* __restrict__ b1)
{
    __shared__ __align__(128) unsigned char As[16384];
    __shared__ __align__(128) unsigned char Bs0[8192], Bs1[8192];
    __shared__ float b0s[64], b1s[64], prb[4][8];

    const int t = threadIdx.x, wid = t >> 5, lane = t & 31;
    const int L = lane & 3;
    const int rcls = wid * 8 + (lane >> 2);

    if (t < 64) { b0s[t] = b0[t]; b1s[t] = b1[t]; }
    if (lane < 8) prb[wid][lane] = 0.f;

    float2 accS[8], accQ[8];
#pragma unroll
    for (int j = 0; j < 8; j++) {
        accS[j] = make_float2(0.f, 0.f);
        accQ[j] = make_float2(0.f, 0.f);
    }

    for (int idx = t; idx < 1024; idx += 128) {
        int j = idx >> 4, k2 = idx & 15;
        int c0 = 2 * k2, c1 = c0 + 1;
        float v0 = (c0 < NF) ? w0[j * NF + c0] : 0.f;
        float v1 = (c1 < NF) ? w0[j * NF + c1] : 0.f;
        *(__nv_bfloat162*)(Bs0 + SW(j * 128 + k2 * 4)) = __floats2bfloat162_rn(v0, v1);
    }
    stage_w(w1, Bs1, t);
    __syncthreads();

    for (int tile = blockIdx.x; tile < NCTA; tile += EDGE_GRID) {
        const int node0 = tile * 2;
        const int b = node0 / NP;
        const int node = node0 + (t >> 6);
        const int m    = t & 63;
        const int jn   = nbr[node * NNB + m];
        const int nidx = b * NP + jn;

        float d0 = pos[nidx * 3 + 0] - pos[node * 3 + 0]; d0 -= rintf(d0);
        float d1 = pos[nidx * 3 + 1] - pos[node * 3 + 1]; d1 -= rintf(d1);
        float d2 = pos[nidx * 3 + 2] - pos[node * 3 + 2]; d2 -= rintf(d2);
        float r2 = d0 * d0 + d1 * d1 + d2 * d2 + 1e-12f;
        float R  = sqrtf(r2);
        float inv = 1.0f / R;

        float Ris[9], Rj[9];
#pragma unroll
        for (int k = 0; k < 9; k++) Ris[k] = orR[node * 9 + k];
#pragma unroll
        for (int k = 0; k < 9; k++) Rj[k]  = orR[nidx * 9 + k];

        float f[NF];
        f[0] = d0 * inv; f[1] = d1 * inv; f[2] = d2 * inv; f[3] = R;
#pragma unroll
        for (int j = 0; j < 3; j++) {
            f[4 + j] = f[0] * Ris[j] + f[1] * Ris[3 + j] + f[2] * Ris[6 + j];
            f[7 + j] = f[0] * Rj[j]  + f[1] * Rj[3 + j]  + f[2] * Rj[6 + j];
        }
#pragma unroll
        for (int j = 0; j < 3; j++)
#pragma unroll
            for (int k = 0; k < 3; k++)
                f[10 + j * 3 + k] = Ris[j] * Rj[k] + Ris[3 + j] * Rj[3 + k] + Ris[6 + j] * Rj[6 + k];

        {   // prior: warp reduce, accumulate per-warp per-batch
            float tp = 0.01f * inv;
            float tp2 = tp * tp, tp4 = tp2 * tp2, tp8 = tp4 * tp4;
            float pr = tp8 * tp4;
#pragma unroll
            for (int off = 16; off > 0; off >>= 1)
                pr += __shfl_xor_sync(0xffffffffu, pr, off);
            if (lane == 0) prb[wid][b] += pr;
        }

#pragma unroll
        for (int j2 = 0; j2 < 16; j2++) {
            float v0 = 0.f, v1 = 0.f;
            if (j2 < 9) { v0 = f[2 * j2]; v1 = f[2 * j2 + 1]; }
            else if (j2 == 9) { v0 = f[18]; }
            *(__nv_bfloat162*)(As + SW(t * 128 + j2 * 4)) = __floats2bfloat162_rn(v0, v1);
        }
        __syncwarp();

        float c[2][8][4];
        mma_layer<2>(As, Bs0, wid, lane, c);

        // layer0 epilogue -> register A-fragments for layer1 (relu + b0, bf16 pack)
        uint32_t ha0[4][4], ha1[4][4];
#pragma unroll
        for (int ks = 0; ks < 4; ks++) {
            const int c0 = ks * 16 + 2 * L;
            float bA0 = b0s[c0], bA1 = b0s[c0 + 1];
            float bB0 = b0s[c0 + 8], bB1 = b0s[c0 + 9];
            ha0[ks][0] = pkrelu(c[0][2 * ks][0] + bA0, c[0][2 * ks][1] + bA1);
            ha0[ks][1] = pkrelu(c[0][2 * ks][2] + bA0, c[0][2 * ks][3] + bA1);
            ha0[ks][2] = pkrelu(c[0][2 * ks + 1][0] + bB0, c[0][2 * ks + 1][1] + bB1);
            ha0[ks][3] = pkrelu(c[0][2 * ks + 1][2] + bB0, c[0][2 * ks + 1][3] + bB1);
            ha1[ks][0] = pkrelu(c[1][2 * ks][0] + bA0, c[1][2 * ks][1] + bA1);
            ha1[ks][1] = pkrelu(c[1][2 * ks][2] + bA0, c[1][2 * ks][3] + bA1);
            ha1[ks][2] = pkrelu(c[1][2 * ks + 1][0] + bB0, c[1][2 * ks + 1][1] + bB1);
            ha1[ks][3] = pkrelu(c[1][2 * ks + 1][2] + bB0, c[1][2 * ks + 1][3] + bB1);
        }

        mma_layer_regA(ha0, ha1, Bs1, lane, c);

        // epilogue 1: +b1, round fp16, store coalesced, accumulate stats in regs
        {
            __half2 o[32];
#pragma unroll
            for (int j = 0; j < 8; j++) {
                const int c0 = j * 8 + L * 2;
                float b0v = b1s[c0], b1v = b1s[c0 + 1];
                __half2 h0 = __floats2half2_rn(c[0][j][0] + b0v, c[0][j][1] + b1v);
                __half2 h1 = __floats2half2_rn(c[0][j][2] + b0v, c[0][j][3] + b1v);
                __half2 h2 = __floats2half2_rn(c[1][j][0] + b0v, c[1][j][1] + b1v);
                __half2 h3 = __floats2half2_rn(c[1][j][2] + b0v, c[1][j][3] + b1v);
                o[j * 2]          = h0;
                o[j * 2 + 1]      = h1;
                o[16 + j * 2]     = h2;
                o[16 + j * 2 + 1] = h3;
                float2 v0 = __half22float2(h0), v1 = __half22float2(h1);
                float2 v2 = __half22float2(h2), v3 = __half22float2(h3);
                accS[j].x += (v0.x + v1.x) + (v2.x + v3.x);
                accS[j].y += (v0.y + v1.y) + (v2.y + v3.y);
                accQ[j].x += (v0.x * v0.x + v1.x * v1.x) + (v2.x * v2.x + v3.x * v3.x);
                accQ[j].y += (v0.y * v0.y + v1.y * v1.y) + (v2.y * v2.y + v3.y * v3.y);
            }
            __half* tbase = g_tbuf + ((size_t)tile * 128 + t) * 64;
#pragma unroll
            for (int q = 0; q < 8; q++) *(uint4*)(tbase + 8 * q) = ((uint4*)o)[q];
        }
    }

    // final stats reduction: overlay As (now dead)
    __syncthreads();
    {
        float2* ps2 = (float2*)As;
        float2* pq2 = (float2*)(As + 8192);
#pragma unroll
        for (int j = 0; j < 8; j++) {
            ps2[rcls * 32 + j * 4 + L] = accS[j];
            pq2[rcls * 32 + j * 4 + L] = accQ[j];
        }
    }
    __syncthreads();
    if (t < 32) {
        const float2* ps2 = (const float2*)As;
        const float2* pq2 = (const float2*)(As + 8192);
        float2 s = make_float2(0.f, 0.f), q = make_float2(0.f, 0.f);
#pragma unroll 8
        for (int r = 0; r < 32; r++) {
            float2 a = ps2[r * 32 + t], qq = pq2[r * 32 + t];
            s.x += a.x; s.y += a.y; q.x += qq.x; q.y += qq.y;
        }
        int c0 = (t >> 2) * 8 + (t & 3) * 2;
        atomicAdd(&g_sum1[c0],     (double)s.x);
        atomicAdd(&g_sum1[c0 + 1], (double)s.y);
        atomicAdd(&g_sq1[c0],      (double)q.x);
        atomicAdd(&g_sq1[c0 + 1],  (double)q.y);
    }
    if (t < 8) {
        float p = (prb[0][t] + prb[1][t]) + (prb[2][t] + prb[3][t]);
        if (p != 0.f) atomicAdd(&g_U0[t], (double)p);
    }
}

// ---------------- stage 2 (persistent, register-A, no As tile) ----------------
__global__ __launch_bounds__(128, 4)
void k_edge2(const float* __restrict__ g1, const float* __restrict__ be1,
             const float* __restrict__ w2, const float* __restrict__ b2)
{
    __shared__ __align__(128) unsigned char Bs[8192];
    __shared__ float2 ps[32 * 33], pq[32 * 33];
    __shared__ float b2s[64], sc[64], sh[64];

    const int t = threadIdx.x, wid = t >> 5, lane = t & 31;
    const int L = lane & 3;

    if (t < 64) {
        b2s[t] = b2[t];
        double mean = g_sum1[t] / (double)NE;
        double var  = g_sq1[t] / (double)NE - mean * mean;
        float istd  = rsqrtf((float)var + 1e-5f);
        float scale = g1[t] * istd;
        sc[t] = scale;
        sh[t] = be1[t] - (float)mean * scale;
    }
    {
        const int rcls = wid * 8 + (lane >> 2);
#pragma unroll
        for (int j = 0; j < 8; j++) {
            ps[rcls * 33 + j * 4 + L] = make_float2(0.f, 0.f);
            pq[rcls * 33 + j * 4 + L] = make_float2(0.f, 0.f);
        }
    }
    stage_w(w2, Bs, t);
    __syncthreads();

    for (int tile = blockIdx.x; tile < NCTA; tile += EDGE_GRID) {
        uint4 rv[8];
        const uint4* rp = (const uint4*)(g_tbuf + ((size_t)tile * 128 + t) * 64);
#pragma unroll
        for (int q = 0; q < 8; q++) rv[q] = rp[q];

        float c[2][8][4];
        zero_c(c);
#pragma unroll
        for (int ks = 0; ks < 4; ks++) {
            uint32_t a0[4], a1[4];
            bn_pack(rv[ks],     sc, sh, ks * 16 + 2 * L, a0);
            bn_pack(rv[4 + ks], sc, sh, ks * 16 + 2 * L, a1);
#pragma unroll
            for (int jt = 0; jt < 4; jt++) {
                uint32_t b[4];
                ldmB(b, Bs, jt * 16, ks * 16, lane);
                MMA16816(c[0][jt * 2],     a0, b[0], b[1]);
                MMA16816(c[0][jt * 2 + 1], a0, b[2], b[3]);
                MMA16816(c[1][jt * 2],     a1, b[0], b[1]);
                MMA16816(c[1][jt * 2 + 1], a1, b[2], b[3]);
            }
        }
        epi_store_stats(c, b2s, g_tbuf + ((size_t)tile * 128 + t) * 64, ps, pq, wid, lane);
    }

    __syncthreads();
    if (t < 32) {
        float2 s = make_float2(0.f, 0.f), q = make_float2(0.f, 0.f);
#pragma unroll 8
        for (int r = 0; r < 32; r++) {
            float2 a = ps[r * 33 + t], qq = pq[r * 33 + t];
            s.x += a.x; s.y += a.y; q.x += qq.x; q.y += qq.y;
        }
        int c0 = (t >> 2) * 8 + (t & 3) * 2;
        atomicAdd(&g_sum2[c0],     (double)s.x);
        atomicAdd(&g_sum2[c0 + 1], (double)s.y);
        atomicAdd(&g_sq2[c0],      (double)q.x);
        atomicAdd(&g_sq2[c0 + 1],  (double)q.y);
    }
}

// ---------------- stage 3 (persistent, register-A) + pooling + fused colmax ----------------
__global__ __launch_bounds__(128, 4)
void k_edge3(const float* __restrict__ g2, const float* __restrict__ be2,
             const float* __restrict__ w3, const float* __restrict__ b3)
{
    __shared__ __align__(128) unsigned char Bs[8192];
    __shared__ float2 ps[32 * 33];
    __shared__ float pm[128];
    __shared__ float b3s[64], sc[64], sh[64];

    const int t = threadIdx.x, wid = t >> 5, lane = t & 31;
    const int L = lane & 3;

    if (t < 64) {
        b3s[t] = b3[t];
        double mean = g_sum2[t] / (double)NE;
        double var  = g_sq2[t] / (double)NE - mean * mean;
        float istd  = rsqrtf((float)var + 1e-5f);
        float scale = g2[t] * istd;
        sc[t] = scale;
        sh[t] = be2[t] - (float)mean * scale;
    }
    stage_w(w3, Bs, t);
    __syncthreads();

    for (int tile = blockIdx.x; tile < NCTA; tile += EDGE_GRID) {
        const int node0 = tile * 2;
        const int b = node0 / NP;

        uint4 rv[8];
        const uint4* rp = (const uint4*)(g_tbuf + ((size_t)tile * 128 + t) * 64);
#pragma unroll
        for (int q = 0; q < 8; q++) rv[q] = rp[q];

        float c[2][8][4];
        zero_c(c);
#pragma unroll
        for (int ks = 0; ks < 4; ks++) {
            uint32_t a0[4], a1[4];
            bn_pack(rv[ks],     sc, sh, ks * 16 + 2 * L, a0);
            bn_pack(rv[4 + ks], sc, sh, ks * 16 + 2 * L, a1);
#pragma unroll
            for (int jt = 0; jt < 4; jt++) {
                uint32_t b2r[4];
                ldmB(b2r, Bs, jt * 16, ks * 16, lane);
                MMA16816(c[0][jt * 2],     a0, b2r[0], b2r[1]);
                MMA16816(c[0][jt * 2 + 1], a0, b2r[2], b2r[3]);
                MMA16816(c[1][jt * 2],     a1, b2r[0], b2r[1]);
                MMA16816(c[1][jt * 2 + 1], a1, b2r[2], b2r[3]);
            }
        }

        {
            const int rcls = wid * 8 + (lane >> 2);
#pragma unroll
            for (int j = 0; j < 8; j++) {
                float sx = (c[0][j][0] + c[0][j][2]) + (c[1][j][0] + c[1][j][2]);
                float sy = (c[0][j][1] + c[0][j][3]) + (c[1][j][1] + c[1][j][3]);
                ps[rcls * 33 + j * 4 + L] = make_float2(sx, sy);
            }
        }
        __syncthreads();

        {
            int nodesel = t >> 6;
            int cidx = t & 63;
            int p = (cidx >> 3) * 4 + ((cidx & 7) >> 1);
            int comp = cidx & 1;
            float s = 0.f;
            int rbase = nodesel * 16;
#pragma unroll 8
            for (int r = 0; r < 16; r++) {
                float2 a = ps[(rbase + r) * 33 + p];
                s += comp ? a.y : a.x;
            }
            s = s * (1.0f / NNB) + b3s[cidx];
            g_pooled[(node0 + nodesel) * HH + cidx] = s;
            pm[t] = s;
        }
        __syncthreads();
        if (t < 64)
            atomicMax(&g_cm[0][b * HH + t], enc_f(fmaxf(pm[t], pm[t + 64])));
    }
}

// ---------------- PermEqui1_max + fused output colmax ----------------
__global__ __launch_bounds__(128) void k_pe(int insel, int cmin, int cmout, int outsel,
    const float* __restrict__ w, const float* __restrict__ bias)
{
    __shared__ float ws[HH * HH], cf[HH], cms[HH];
    __shared__ float wm[HH * 4];
    const int bx = blockIdx.x;
    const int b  = bx >> 4;
    const int rb = bx & 15;
    const int t  = threadIdx.x;
    const int wid = t >> 5, lane = t & 31;
    const float* zin = selz(insel);
    float* zout = (outsel == 1) ? g_zA : ((outsel == 2) ? g_zB : 0);

    for (int i = t; i < HH * HH; i += 128) ws[i] = w[i];
    if (t < HH) cms[t] = dec_f(g_cm[cmin][b * HH + t]);
    __syncthreads();

    if (t < HH) {
        float a0 = bias[t], a1 = 0.f, a2 = 0.f, a3 = 0.f;
#pragma unroll
        for (int h = 0; h < HH; h += 4) {
            a0 -= cms[h]     * ws[t * 64 + h];
            a1 -= cms[h + 1] * ws[t * 64 + h + 1];
            a2 -= cms[h + 2] * ws[t * 64 + h + 2];
            a3 -= cms[h + 3] * ws[t * 64 + h + 3];
        }
        cf[t] = (a0 + a1) + (a2 + a3);
    }
    __syncthreads();

    const int n = rb * 125 + t;
    const bool valid = (t < 125);
    float z[HH];
    const float* zr = &zin[((size_t)b * NP + (valid ? n : 0)) * HH];
#pragma unroll
    for (int h = 0; h < HH; h++) z[h] = zr[h];
    float* orow = zout ? &zout[((size_t)b * NP + n) * HH] : 0;

#pragma unroll 4
    for (int fj = 0; fj < HH; fj++) {
        float a0 = cf[fj], a1 = 0.f, a2 = 0.f, a3 = 0.f;
#pragma unroll
        for (int h = 0; h < HH; h += 4) {
            a0 += z[h]     * ws[fj * 64 + h];
            a1 += z[h + 1] * ws[fj * 64 + h + 1];
            a2 += z[h + 2] * ws[fj * 64 + h + 2];
            a3 += z[h + 3] * ws[fj * 64 + h + 3];
        }
        float v = tanhf((a0 + a1) + (a2 + a3));
        if (valid && orow) orow[fj] = v;
        float mv = valid ? v : -INFINITY;
#pragma unroll
        for (int off = 16; off > 0; off >>= 1)
            mv = fmaxf(mv, __shfl_xor_sync(0xffffffffu, mv, off));
        if (lane == 0) wm[fj * 4 + wid] = mv;
    }
    __syncthreads();
    if (t < HH) {
        float m = fmaxf(fmaxf(wm[t * 4], wm[t * 4 + 1]), fmaxf(wm[t * 4 + 2], wm[t * 4 + 3]));
        atomicMax(&g_cm[cmout][b * HH + t], enc_f(m));
    }
}

// ---------------- head ----------------
__global__ __launch_bounds__(64) void k_head(
    const float* __restrict__ r1w, const float* __restrict__ r1b,
    const float* __restrict__ r2w, const float* __restrict__ r2b,
    float* __restrict__ out)
{
    const int b = blockIdx.x;
    const int f = threadIdx.x;
    __shared__ float s[HH], tv[HH];

    s[f] = dec_f(g_cm[3][b * HH + f]);
    __syncthreads();

    float a = r1b[f];
#pragma unroll
    for (int h = 0; h < HH; h++) a += s[h] * r1w[f * 64 + h];
    tv[f] = tanhf(a);
    __syncthreads();

    if (f == 0) {
        float e = r2b[0];
        for (int h = 0; h < HH; h++) e += tv[h] * r2w[h];
        out[b] = e + (float)g_U0[b];
    }
}

// ---------------- launcher ----------------
extern "C" void kernel_launch(void* const* d_in, const int* in_sizes, int n_in,
                              void* d_out, int out_size)
{
    const float* pos = (const float*)d_in[0];
    const float* orR = (const float*)d_in[1];
    const int*   nbr = (const int*)  d_in[2];
    const float* w0  = (const float*)d_in[3];
    const float* b0  = (const float*)d_in[4];
    const float* w1  = (const float*)d_in[5];
    const float* b1  = (const float*)d_in[6];
    const float* g1  = (const float*)d_in[7];
    const float* be1 = (const float*)d_in[8];
    const float* w2  = (const float*)d_in[9];
    const float* b2  = (const float*)d_in[10];
    const float* g2  = (const float*)d_in[11];
    const float* be2 = (const float*)d_in[12];
    const float* w3  = (const float*)d_in[13];
    const float* b3  = (const float*)d_in[14];
    const float* p1w = (const float*)d_in[15];
    const float* p1b = (const float*)d_in[16];
    const float* p2w = (const float*)d_in[17];
    const float* p2b = (const float*)d_in[18];
    const float* p3w = (const float*)d_in[19];
    const float* p3b = (const float*)d_in[20];
    const float* r1w = (const float*)d_in[21];
    const float* r1b = (const float*)d_in[22];
    const float* r2w = (const float*)d_in[23];
    const float* r2b = (const float*)d_in[24];
    float* out = (float*)d_out;

    k_zero <<<1, 512>>>();
    k_edge1<<<EDGE_GRID, 128>>>(pos, orR, nbr, w0, b0, w1, b1);
    k_edge2<<<EDGE_GRID, 128>>>(g1, be1, w2, b2);
    k_edge3<<<EDGE_GRID, 128>>>(g2, be2, w3, b3);
    k_pe   <<<BB * 16, 128>>>(0, 0, 1, 1, p1w, p1b);
    k_pe   <<<BB * 16, 128>>>(1, 1, 2, 2, p2w, p2b);
    k_pe   <<<BB * 16, 128>>>(2, 2, 3, 0, p3w, p3b);
    k_head <<<BB, 64>>>(r1w, r1b, r2w, r2b, out);
}